// round 1
// baseline (speedup 1.0000x reference)
#include <cuda_runtime.h>
#include <cuda_bf16.h>
#include <cstdint>

// Problem constants
#define N_NODES 100000
#define E_EDGES 1600000
#define F_IN 64
#define H_DIM 128

// ---------------- device scratch (no runtime allocation allowed) ----------------
__device__ int   g_cnt[N_NODES];           // in-degree per dst node
__device__ int   g_off[N_NODES];           // CSR offsets (exclusive scan of cnt)
__device__ int   g_cur[N_NODES];           // scatter cursors
__device__ int   g_srcs[E_EDGES];          // src node ids grouped by dst
__device__ int   g_blocksums[128];         // scan partials
__device__ float g_mean1[(size_t)N_NODES * F_IN];   // layer-1 mean aggregate
__device__ float g_h[(size_t)N_NODES * H_DIM];      // layer-1 output (post relu)
__device__ float g_mean2[(size_t)N_NODES * H_DIM];  // layer-2 mean aggregate

// ---------------- CSR build ----------------
__global__ void zero_cnt_kernel() {
    int i = blockIdx.x * blockDim.x + threadIdx.x;
    if (i < N_NODES) g_cnt[i] = 0;
}

__global__ void count_kernel(const int* __restrict__ ei) {
    int e = blockIdx.x * blockDim.x + threadIdx.x;
    if (e < E_EDGES) atomicAdd(&g_cnt[ei[E_EDGES + e]], 1);
}

// blockDim = 1024; per-block exclusive scan (Hillis-Steele) + block total
__global__ void scan_local_kernel() {
    __shared__ int s[1024];
    int i = blockIdx.x * 1024 + threadIdx.x;
    int v = (i < N_NODES) ? g_cnt[i] : 0;
    s[threadIdx.x] = v;
    __syncthreads();
    for (int d = 1; d < 1024; d <<= 1) {
        int t = (threadIdx.x >= d) ? s[threadIdx.x - d] : 0;
        __syncthreads();
        s[threadIdx.x] += t;
        __syncthreads();
    }
    if (i < N_NODES) g_off[i] = s[threadIdx.x] - v;  // exclusive
    if (threadIdx.x == 1023) g_blocksums[blockIdx.x] = s[1023];
}

// single block of 128 threads: exclusive scan of block sums (NBLK <= 128)
__global__ void scan_top_kernel(int nblk) {
    __shared__ int s[128];
    int v = (threadIdx.x < nblk) ? g_blocksums[threadIdx.x] : 0;
    s[threadIdx.x] = v;
    __syncthreads();
    for (int d = 1; d < 128; d <<= 1) {
        int t = (threadIdx.x >= d) ? s[threadIdx.x - d] : 0;
        __syncthreads();
        s[threadIdx.x] += t;
        __syncthreads();
    }
    if (threadIdx.x < nblk) g_blocksums[threadIdx.x] = s[threadIdx.x] - v;
}

__global__ void scan_add_kernel() {
    int i = blockIdx.x * 1024 + threadIdx.x;
    if (i < N_NODES) {
        int o = g_off[i] + g_blocksums[blockIdx.x];
        g_off[i] = o;
        g_cur[i] = o;
    }
}

__global__ void scatter_kernel(const int* __restrict__ ei) {
    int e = blockIdx.x * blockDim.x + threadIdx.x;
    if (e < E_EDGES) {
        int d = ei[E_EDGES + e];
        int p = atomicAdd(&g_cur[d], 1);
        g_srcs[p] = ei[e];
    }
}

// ---------------- aggregation (mean of src features per dst) ----------------
// Layer 1: 64 features -> 16 float4 chunks; 16 lanes per node.
__global__ void agg1_kernel(const float* __restrict__ x) {
    int t = blockIdx.x * blockDim.x + threadIdx.x;
    int n = t >> 4;
    int c = t & 15;
    if (n >= N_NODES) return;
    int start = g_off[n];
    int deg = g_cnt[n];
    const float4* x4 = (const float4*)x;
    float4 a0 = make_float4(0.f, 0.f, 0.f, 0.f);
    float4 a1 = a0, a2 = a0, a3 = a0;
    int i = 0;
    for (; i + 4 <= deg; i += 4) {
        int s0 = g_srcs[start + i + 0];
        int s1 = g_srcs[start + i + 1];
        int s2 = g_srcs[start + i + 2];
        int s3 = g_srcs[start + i + 3];
        float4 v0 = x4[(size_t)s0 * 16 + c];
        float4 v1 = x4[(size_t)s1 * 16 + c];
        float4 v2 = x4[(size_t)s2 * 16 + c];
        float4 v3 = x4[(size_t)s3 * 16 + c];
        a0.x += v0.x; a0.y += v0.y; a0.z += v0.z; a0.w += v0.w;
        a1.x += v1.x; a1.y += v1.y; a1.z += v1.z; a1.w += v1.w;
        a2.x += v2.x; a2.y += v2.y; a2.z += v2.z; a2.w += v2.w;
        a3.x += v3.x; a3.y += v3.y; a3.z += v3.z; a3.w += v3.w;
    }
    for (; i < deg; i++) {
        int s0 = g_srcs[start + i];
        float4 v0 = x4[(size_t)s0 * 16 + c];
        a0.x += v0.x; a0.y += v0.y; a0.z += v0.z; a0.w += v0.w;
    }
    a0.x += a1.x + a2.x + a3.x;
    a0.y += a1.y + a2.y + a3.y;
    a0.z += a1.z + a2.z + a3.z;
    a0.w += a1.w + a2.w + a3.w;
    float inv = 1.0f / (float)(deg > 0 ? deg : 1);
    float4 r = make_float4(a0.x * inv, a0.y * inv, a0.z * inv, a0.w * inv);
    ((float4*)g_mean1)[(size_t)n * 16 + c] = r;
}

// Layer 2: 128 features -> 32 float4 chunks; full warp per node.
__global__ void agg2_kernel() {
    int t = blockIdx.x * blockDim.x + threadIdx.x;
    int n = t >> 5;
    int c = t & 31;
    if (n >= N_NODES) return;
    int start = g_off[n];
    int deg = g_cnt[n];
    const float4* h4 = (const float4*)g_h;
    float4 a0 = make_float4(0.f, 0.f, 0.f, 0.f);
    float4 a1 = a0, a2 = a0, a3 = a0;
    int i = 0;
    for (; i + 4 <= deg; i += 4) {
        int s0 = g_srcs[start + i + 0];
        int s1 = g_srcs[start + i + 1];
        int s2 = g_srcs[start + i + 2];
        int s3 = g_srcs[start + i + 3];
        float4 v0 = h4[(size_t)s0 * 32 + c];
        float4 v1 = h4[(size_t)s1 * 32 + c];
        float4 v2 = h4[(size_t)s2 * 32 + c];
        float4 v3 = h4[(size_t)s3 * 32 + c];
        a0.x += v0.x; a0.y += v0.y; a0.z += v0.z; a0.w += v0.w;
        a1.x += v1.x; a1.y += v1.y; a1.z += v1.z; a1.w += v1.w;
        a2.x += v2.x; a2.y += v2.y; a2.z += v2.z; a2.w += v2.w;
        a3.x += v3.x; a3.y += v3.y; a3.z += v3.z; a3.w += v3.w;
    }
    for (; i < deg; i++) {
        int s0 = g_srcs[start + i];
        float4 v0 = h4[(size_t)s0 * 32 + c];
        a0.x += v0.x; a0.y += v0.y; a0.z += v0.z; a0.w += v0.w;
    }
    a0.x += a1.x + a2.x + a3.x;
    a0.y += a1.y + a2.y + a3.y;
    a0.z += a1.z + a2.z + a3.z;
    a0.w += a1.w + a2.w + a3.w;
    float inv = 1.0f / (float)(deg > 0 ? deg : 1);
    float4 r = make_float4(a0.x * inv, a0.y * inv, a0.z * inv, a0.w * inv);
    ((float4*)g_mean2)[(size_t)n * 32 + c] = r;
}

// ---------------- fused dual GEMM: out = Amean@Wl^T + bl + Aself@Wr^T (opt relu) ----------------
// K = per-operand inner dim (64 or 128). H = 128 output cols.
// blockDim = 256. Thread layout: cg = tid&31 (4 cols each), rs = tid>>5 (rows rs, rs+8, rs+16, rs+24).
// smem: Ws[2K][128] transposed weights, As[32][2K] input tile.
template <int K>
__global__ __launch_bounds__(256) void gemm_kernel(
    const float* __restrict__ Amean, const float* __restrict__ Aself,
    const float* __restrict__ Wl, const float* __restrict__ bl,
    const float* __restrict__ Wr, float* __restrict__ out, int relu)
{
    constexpr int KK = 2 * K;
    extern __shared__ float sm[];
    float* Ws = sm;               // KK * 128
    float* As = sm + KK * 128;    // 32 * KK
    int tid = threadIdx.x;

    // load combined transposed weights: Ws[k*128 + j]
    for (int idx = tid; idx < KK * 128; idx += 256) {
        int k = idx >> 7;
        int j = idx & 127;
        Ws[idx] = (k < K) ? Wl[j * K + k] : Wr[j * K + (k - K)];
    }

    int cg = tid & 31;
    int rs = tid >> 5;
    const float4* Ws4 = (const float4*)Ws;
    const int numTiles = N_NODES / 32;

    for (int t = blockIdx.x; t < numTiles; t += gridDim.x) {
        int row0 = t * 32;
        __syncthreads();  // weights ready (1st iter) / prev-iter reads done
        // load 32-row input tile: As[r*KK + k] = [mean | self]
        for (int idx = tid; idx < 32 * (KK / 4); idx += 256) {
            int r = idx / (KK / 4);
            int k4 = idx % (KK / 4);
            float4 v;
            if (k4 < K / 4)
                v = ((const float4*)(Amean + (size_t)(row0 + r) * K))[k4];
            else
                v = ((const float4*)(Aself + (size_t)(row0 + r) * K))[k4 - K / 4];
            ((float4*)(As + r * KK))[k4] = v;
        }
        __syncthreads();

        float4 acc0 = make_float4(0.f, 0.f, 0.f, 0.f);
        float4 acc1 = acc0, acc2 = acc0, acc3 = acc0;
        const float* A0 = As + (rs + 0) * KK;
        const float* A1 = As + (rs + 8) * KK;
        const float* A2 = As + (rs + 16) * KK;
        const float* A3 = As + (rs + 24) * KK;
#pragma unroll 8
        for (int k = 0; k < KK; k++) {
            float4 w = Ws4[k * 32 + cg];
            float a0 = A0[k], a1 = A1[k], a2 = A2[k], a3 = A3[k];
            acc0.x += w.x * a0; acc0.y += w.y * a0; acc0.z += w.z * a0; acc0.w += w.w * a0;
            acc1.x += w.x * a1; acc1.y += w.y * a1; acc1.z += w.z * a1; acc1.w += w.w * a1;
            acc2.x += w.x * a2; acc2.y += w.y * a2; acc2.z += w.z * a2; acc2.w += w.w * a2;
            acc3.x += w.x * a3; acc3.y += w.y * a3; acc3.z += w.z * a3; acc3.w += w.w * a3;
        }
        float4 b = ((const float4*)bl)[cg];
        acc0.x += b.x; acc0.y += b.y; acc0.z += b.z; acc0.w += b.w;
        acc1.x += b.x; acc1.y += b.y; acc1.z += b.z; acc1.w += b.w;
        acc2.x += b.x; acc2.y += b.y; acc2.z += b.z; acc2.w += b.w;
        acc3.x += b.x; acc3.y += b.y; acc3.z += b.z; acc3.w += b.w;
        if (relu) {
            acc0.x = fmaxf(acc0.x, 0.f); acc0.y = fmaxf(acc0.y, 0.f); acc0.z = fmaxf(acc0.z, 0.f); acc0.w = fmaxf(acc0.w, 0.f);
            acc1.x = fmaxf(acc1.x, 0.f); acc1.y = fmaxf(acc1.y, 0.f); acc1.z = fmaxf(acc1.z, 0.f); acc1.w = fmaxf(acc1.w, 0.f);
            acc2.x = fmaxf(acc2.x, 0.f); acc2.y = fmaxf(acc2.y, 0.f); acc2.z = fmaxf(acc2.z, 0.f); acc2.w = fmaxf(acc2.w, 0.f);
            acc3.x = fmaxf(acc3.x, 0.f); acc3.y = fmaxf(acc3.y, 0.f); acc3.z = fmaxf(acc3.z, 0.f); acc3.w = fmaxf(acc3.w, 0.f);
        }
        float4* o = (float4*)out;
        o[((size_t)(row0 + rs + 0) * 128 + cg * 4) / 4] = acc0;
        o[((size_t)(row0 + rs + 8) * 128 + cg * 4) / 4] = acc1;
        o[((size_t)(row0 + rs + 16) * 128 + cg * 4) / 4] = acc2;
        o[((size_t)(row0 + rs + 24) * 128 + cg * 4) / 4] = acc3;
    }
}

// ---------------- launch ----------------
extern "C" void kernel_launch(void* const* d_in, const int* in_sizes, int n_in,
                              void* d_out, int out_size)
{
    const float* x   = (const float*)d_in[0];
    const int*   ei  = (const int*)d_in[1];     // [2, E]: src row then dst row
    const float* Wl1 = (const float*)d_in[2];
    const float* bl1 = (const float*)d_in[3];
    const float* Wr1 = (const float*)d_in[4];
    const float* Wl2 = (const float*)d_in[5];
    const float* bl2 = (const float*)d_in[6];
    const float* Wr2 = (const float*)d_in[7];
    float* out = (float*)d_out;

    // raise smem limits for the GEMMs (idempotent; not a graph op)
    static bool attr_done = false;
    if (!attr_done) {
        cudaFuncSetAttribute(gemm_kernel<64>, cudaFuncAttributeMaxDynamicSharedMemorySize,
                             (2 * 64 * 128 + 32 * 2 * 64) * sizeof(float));
        cudaFuncSetAttribute(gemm_kernel<128>, cudaFuncAttributeMaxDynamicSharedMemorySize,
                             (2 * 128 * 128 + 32 * 2 * 128) * sizeof(float));
        attr_done = true;
    }

    const int NBLK = (N_NODES + 1023) / 1024;   // 98

    // CSR build
    zero_cnt_kernel<<<(N_NODES + 255) / 256, 256>>>();
    count_kernel<<<(E_EDGES + 255) / 256, 256>>>(ei);
    scan_local_kernel<<<NBLK, 1024>>>();
    scan_top_kernel<<<1, 128>>>(NBLK);
    scan_add_kernel<<<NBLK, 1024>>>();
    scatter_kernel<<<(E_EDGES + 255) / 256, 256>>>(ei);

    // resolve device-global addresses (host side, cached, no graph impact)
    static float *p_mean1 = nullptr, *p_h = nullptr, *p_mean2 = nullptr;
    if (!p_mean1) {
        cudaGetSymbolAddress((void**)&p_mean1, g_mean1);
        cudaGetSymbolAddress((void**)&p_h, g_h);
        cudaGetSymbolAddress((void**)&p_mean2, g_mean2);
    }

    // Layer 1: aggregate x, then h = mean1@Wl1^T + bl1 + x@Wr1^T, relu
    agg1_kernel<<<(N_NODES * 16 + 255) / 256, 256>>>(x);
    {
        size_t smem = (size_t)(2 * 64 * 128 + 32 * 2 * 64) * sizeof(float);  // 80 KB
        gemm_kernel<64><<<296, 256, smem>>>(p_mean1, x, Wl1, bl1, Wr1, p_h, 1);
    }

    // Layer 2: aggregate h, then out = mean2@Wl2^T + bl2 + h@Wr2^T
    agg2_kernel<<<(N_NODES * 32 + 255) / 256, 256>>>();
    {
        size_t smem = (size_t)(2 * 128 * 128 + 32 * 2 * 128) * sizeof(float);  // 160 KB
        gemm_kernel<128><<<148, 256, smem>>>(p_mean2, p_h, Wl2, bl2, Wr2, out, 0);
    }
}

// round 2
// speedup vs baseline: 1.5226x; 1.5226x over previous
#include <cuda_runtime.h>
#include <cuda_bf16.h>
#include <cstdint>

// Problem constants
#define N_NODES 100000
#define E_EDGES 1600000
#define F_IN 64
#define H_DIM 128

// ---------------- device scratch (no runtime allocation allowed) ----------------
__device__ int   g_cnt[N_NODES];           // in-degree per dst node
__device__ int   g_off[N_NODES];           // CSR offsets (exclusive scan of cnt)
__device__ int   g_cur[N_NODES];           // scatter cursors
__device__ int   g_srcs[E_EDGES];          // src node ids grouped by dst
__device__ int   g_blocksums[128];         // scan partials
__device__ float g_mean1[(size_t)N_NODES * F_IN];   // layer-1 mean aggregate
__device__ float g_h[(size_t)N_NODES * H_DIM];      // layer-1 output (post relu)
__device__ float g_mean2[(size_t)N_NODES * H_DIM];  // layer-2 mean aggregate

// ---------------- CSR build ----------------
__global__ void zero_cnt_kernel() {
    int i = blockIdx.x * blockDim.x + threadIdx.x;
    if (i < N_NODES) g_cnt[i] = 0;
}

__global__ void count_kernel(const int* __restrict__ ei) {
    int e = blockIdx.x * blockDim.x + threadIdx.x;
    if (e < E_EDGES) atomicAdd(&g_cnt[ei[E_EDGES + e]], 1);
}

// blockDim = 1024; per-block exclusive scan (Hillis-Steele) + block total
__global__ void scan_local_kernel() {
    __shared__ int s[1024];
    int i = blockIdx.x * 1024 + threadIdx.x;
    int v = (i < N_NODES) ? g_cnt[i] : 0;
    s[threadIdx.x] = v;
    __syncthreads();
    for (int d = 1; d < 1024; d <<= 1) {
        int t = (threadIdx.x >= d) ? s[threadIdx.x - d] : 0;
        __syncthreads();
        s[threadIdx.x] += t;
        __syncthreads();
    }
    if (i < N_NODES) g_off[i] = s[threadIdx.x] - v;  // exclusive (local)
    if (threadIdx.x == 1023) g_blocksums[blockIdx.x] = s[1023];
}

// Each block redundantly scans the (<=128) block sums in smem, then adds its
// prefix and writes final offsets + cursors. Folds old scan_top + scan_add.
__global__ void scan_finish_kernel(int nblk) {
    __shared__ int bs[128];
    if (threadIdx.x < 128)
        bs[threadIdx.x] = (threadIdx.x < nblk) ? g_blocksums[threadIdx.x] : 0;
    __syncthreads();
    if (threadIdx.x == 0) {
        int run = 0;
        for (int b = 0; b < nblk; b++) { int v = bs[b]; bs[b] = run; run += v; }
    }
    __syncthreads();
    int i = blockIdx.x * 1024 + threadIdx.x;
    if (i < N_NODES) {
        int o = g_off[i] + bs[blockIdx.x];
        g_off[i] = o;
        g_cur[i] = o;
    }
}

__global__ void scatter_kernel(const int* __restrict__ ei) {
    int e = blockIdx.x * blockDim.x + threadIdx.x;
    if (e < E_EDGES) {
        int d = ei[E_EDGES + e];
        int p = atomicAdd(&g_cur[d], 1);
        g_srcs[p] = ei[e];
    }
}

// ---------------- aggregation (mean of src features per dst) ----------------
// Layer 1: 64 features -> 16 float4 chunks; 16 lanes per node.
__global__ void agg1_kernel(const float* __restrict__ x) {
    int t = blockIdx.x * blockDim.x + threadIdx.x;
    int n = t >> 4;
    int c = t & 15;
    if (n >= N_NODES) return;
    int start = g_off[n];
    int deg = g_cnt[n];
    const float4* x4 = (const float4*)x;
    float4 a0 = make_float4(0.f, 0.f, 0.f, 0.f);
    float4 a1 = a0, a2 = a0, a3 = a0;
    int i = 0;
    for (; i + 4 <= deg; i += 4) {
        int s0 = g_srcs[start + i + 0];
        int s1 = g_srcs[start + i + 1];
        int s2 = g_srcs[start + i + 2];
        int s3 = g_srcs[start + i + 3];
        float4 v0 = x4[(size_t)s0 * 16 + c];
        float4 v1 = x4[(size_t)s1 * 16 + c];
        float4 v2 = x4[(size_t)s2 * 16 + c];
        float4 v3 = x4[(size_t)s3 * 16 + c];
        a0.x += v0.x; a0.y += v0.y; a0.z += v0.z; a0.w += v0.w;
        a1.x += v1.x; a1.y += v1.y; a1.z += v1.z; a1.w += v1.w;
        a2.x += v2.x; a2.y += v2.y; a2.z += v2.z; a2.w += v2.w;
        a3.x += v3.x; a3.y += v3.y; a3.z += v3.z; a3.w += v3.w;
    }
    for (; i < deg; i++) {
        int s0 = g_srcs[start + i];
        float4 v0 = x4[(size_t)s0 * 16 + c];
        a0.x += v0.x; a0.y += v0.y; a0.z += v0.z; a0.w += v0.w;
    }
    a0.x += a1.x + a2.x + a3.x;
    a0.y += a1.y + a2.y + a3.y;
    a0.z += a1.z + a2.z + a3.z;
    a0.w += a1.w + a2.w + a3.w;
    float inv = 1.0f / (float)(deg > 0 ? deg : 1);
    float4 r = make_float4(a0.x * inv, a0.y * inv, a0.z * inv, a0.w * inv);
    ((float4*)g_mean1)[(size_t)n * 16 + c] = r;
}

// Layer 2: 128 features -> 32 float4 chunks; full warp per node.
__global__ void agg2_kernel() {
    int t = blockIdx.x * blockDim.x + threadIdx.x;
    int n = t >> 5;
    int c = t & 31;
    if (n >= N_NODES) return;
    int start = g_off[n];
    int deg = g_cnt[n];
    const float4* h4 = (const float4*)g_h;
    float4 a0 = make_float4(0.f, 0.f, 0.f, 0.f);
    float4 a1 = a0, a2 = a0, a3 = a0;
    int i = 0;
    for (; i + 4 <= deg; i += 4) {
        int s0 = g_srcs[start + i + 0];
        int s1 = g_srcs[start + i + 1];
        int s2 = g_srcs[start + i + 2];
        int s3 = g_srcs[start + i + 3];
        float4 v0 = h4[(size_t)s0 * 32 + c];
        float4 v1 = h4[(size_t)s1 * 32 + c];
        float4 v2 = h4[(size_t)s2 * 32 + c];
        float4 v3 = h4[(size_t)s3 * 32 + c];
        a0.x += v0.x; a0.y += v0.y; a0.z += v0.z; a0.w += v0.w;
        a1.x += v1.x; a1.y += v1.y; a1.z += v1.z; a1.w += v1.w;
        a2.x += v2.x; a2.y += v2.y; a2.z += v2.z; a2.w += v2.w;
        a3.x += v3.x; a3.y += v3.y; a3.z += v3.z; a3.w += v3.w;
    }
    for (; i < deg; i++) {
        int s0 = g_srcs[start + i];
        float4 v0 = h4[(size_t)s0 * 32 + c];
        a0.x += v0.x; a0.y += v0.y; a0.z += v0.z; a0.w += v0.w;
    }
    a0.x += a1.x + a2.x + a3.x;
    a0.y += a1.y + a2.y + a3.y;
    a0.z += a1.z + a2.z + a3.z;
    a0.w += a1.w + a2.w + a3.w;
    float inv = 1.0f / (float)(deg > 0 ? deg : 1);
    float4 r = make_float4(a0.x * inv, a0.y * inv, a0.z * inv, a0.w * inv);
    ((float4*)g_mean2)[(size_t)n * 32 + c] = r;
}

// ---------------- tf32 tensor-core dual GEMM ----------------
// out[M,128] = [Amean | Aself] @ [Wl ; Wr]^T + bl  (optional relu)
// KK = 2K inner dim. Block: 256 thr (8 warps), tile 128 rows x 128 cols.
// Warp w: rows [16w,16w+16), all 128 cols as 16 m16n8 tiles.
// B held in smem in fragment order; A staged per-64-col chunk, stride-68 rows
// (68 mod 32 == 4 -> m16n8k8 a-frag LDS is conflict-free).

__device__ __forceinline__ unsigned f2tf32(float f) {
    unsigned u;
    asm("cvt.rna.tf32.f32 %0, %1;" : "=r"(u) : "f"(f));
    return u;
}

__device__ __forceinline__ void mma_tf32(float* acc, unsigned a0, unsigned a1,
                                         unsigned a2, unsigned a3,
                                         unsigned b0, unsigned b1) {
    asm volatile(
        "mma.sync.aligned.m16n8k8.row.col.f32.tf32.tf32.f32 "
        "{%0,%1,%2,%3}, {%4,%5,%6,%7}, {%8,%9}, {%0,%1,%2,%3};"
        : "+f"(acc[0]), "+f"(acc[1]), "+f"(acc[2]), "+f"(acc[3])
        : "r"(a0), "r"(a1), "r"(a2), "r"(a3), "r"(b0), "r"(b1));
}

template <int K, int RELU>
__global__ __launch_bounds__(256) void mma_gemm_kernel(
    const float* __restrict__ Amean, const float* __restrict__ Aself,
    const float* __restrict__ Wl, const float* __restrict__ bl,
    const float* __restrict__ Wr, float* __restrict__ out)
{
    constexpr int KK = 2 * K;
    constexpr int NCHUNK = KK / 64;
    constexpr int NFRAG = (KK / 8) * 16;     // ksteps * ntiles
    extern __shared__ unsigned smu[];
    unsigned* Bs = smu;                       // NFRAG * 64
    unsigned* As = smu + NFRAG * 64;          // 128 * 68

    const int tid = threadIdx.x;
    const int lane = tid & 31;
    const int warp = tid >> 5;
    const int gid = lane >> 2;                // group id (0..7)
    const int tig = lane & 3;                 // thread in group

    // Build B fragments: frag (s, nt) holds k in [8s,8s+8), n in [8nt,8nt+8)
    // layout: Bs[frag*64 + lane*2 + reg]; b_reg: k = 8s + tig + 4*reg, n = 8nt + gid
    for (int idx = tid; idx < NFRAG * 64; idx += 256) {
        int frag = idx >> 6;
        int rem = idx & 63;
        int l = rem >> 1;
        int reg = rem & 1;
        int s = frag >> 4;
        int nt = frag & 15;
        int k = s * 8 + (l & 3) + reg * 4;
        int n = nt * 8 + (l >> 2);
        float v = (k < K) ? Wl[n * K + k] : Wr[n * K + (k - K)];
        Bs[idx] = f2tf32(v);
    }

    const int numTiles = (N_NODES + 127) / 128;   // 782
    for (int t = blockIdx.x; t < numTiles; t += gridDim.x) {
        int row0 = t * 128;
        float acc[16][4];
#pragma unroll
        for (int nt = 0; nt < 16; nt++)
#pragma unroll
            for (int r = 0; r < 4; r++) acc[nt][r] = 0.f;

        for (int c = 0; c < NCHUNK; c++) {
            const float* src = (c * 64 < K) ? Amean : Aself;
            int coff = (c * 64 < K) ? c * 64 : c * 64 - K;
            __syncthreads();
            // stage A chunk [128 rows x 64 cols] as tf32, stride 68
#pragma unroll
            for (int i = 0; i < 8; i++) {
                int f4 = tid + i * 256;
                int r = f4 >> 4;
                int j = f4 & 15;
                float4 v = make_float4(0.f, 0.f, 0.f, 0.f);
                int grow = row0 + r;
                if (grow < N_NODES)
                    v = *(const float4*)(src + (size_t)grow * K + coff + j * 4);
                uint4 u;
                u.x = f2tf32(v.x); u.y = f2tf32(v.y);
                u.z = f2tf32(v.z); u.w = f2tf32(v.w);
                *(uint4*)(As + r * 68 + j * 4) = u;
            }
            __syncthreads();

            const int wrow = warp * 16;
#pragma unroll
            for (int s = 0; s < 8; s++) {
                unsigned a0 = As[(wrow + gid) * 68 + s * 8 + tig];
                unsigned a1 = As[(wrow + gid + 8) * 68 + s * 8 + tig];
                unsigned a2 = As[(wrow + gid) * 68 + s * 8 + tig + 4];
                unsigned a3 = As[(wrow + gid + 8) * 68 + s * 8 + tig + 4];
                int sg = c * 8 + s;
#pragma unroll
                for (int nt = 0; nt < 16; nt++) {
                    uint2 b = *(const uint2*)(Bs + (sg * 16 + nt) * 64 + lane * 2);
                    mma_tf32(acc[nt], a0, a1, a2, a3, b.x, b.y);
                }
            }
        }

        // epilogue: bias (+relu) + store
        int r0 = row0 + warp * 16 + gid;
        int r1 = r0 + 8;
#pragma unroll
        for (int nt = 0; nt < 16; nt++) {
            int col = nt * 8 + tig * 2;
            float2 bb = *(const float2*)(bl + col);
            float c0 = acc[nt][0] + bb.x;
            float c1 = acc[nt][1] + bb.y;
            float c2 = acc[nt][2] + bb.x;
            float c3 = acc[nt][3] + bb.y;
            if (RELU) {
                c0 = fmaxf(c0, 0.f); c1 = fmaxf(c1, 0.f);
                c2 = fmaxf(c2, 0.f); c3 = fmaxf(c3, 0.f);
            }
            if (r0 < N_NODES)
                *(float2*)(out + (size_t)r0 * 128 + col) = make_float2(c0, c1);
            if (r1 < N_NODES)
                *(float2*)(out + (size_t)r1 * 128 + col) = make_float2(c2, c3);
        }
    }
}

// ---------------- launch ----------------
extern "C" void kernel_launch(void* const* d_in, const int* in_sizes, int n_in,
                              void* d_out, int out_size)
{
    const float* x   = (const float*)d_in[0];
    const int*   ei  = (const int*)d_in[1];     // [2, E]: src row then dst row
    const float* Wl1 = (const float*)d_in[2];
    const float* bl1 = (const float*)d_in[3];
    const float* Wr1 = (const float*)d_in[4];
    const float* Wl2 = (const float*)d_in[5];
    const float* bl2 = (const float*)d_in[6];
    const float* Wr2 = (const float*)d_in[7];
    float* out = (float*)d_out;

    const int SMEM1 = (2 * 64 * 128) * 4 + 128 * 68 * 4;    // 100352 B
    const int SMEM2 = (2 * 128 * 128) * 4 + 128 * 68 * 4;   // 165888 B

    static bool attr_done = false;
    if (!attr_done) {
        cudaFuncSetAttribute(mma_gemm_kernel<64, 1>,
                             cudaFuncAttributeMaxDynamicSharedMemorySize, SMEM1);
        cudaFuncSetAttribute(mma_gemm_kernel<128, 0>,
                             cudaFuncAttributeMaxDynamicSharedMemorySize, SMEM2);
        attr_done = true;
    }

    const int NBLK = (N_NODES + 1023) / 1024;   // 98

    // CSR build
    zero_cnt_kernel<<<(N_NODES + 255) / 256, 256>>>();
    count_kernel<<<(E_EDGES + 255) / 256, 256>>>(ei);
    scan_local_kernel<<<NBLK, 1024>>>();
    scan_finish_kernel<<<NBLK, 1024>>>(NBLK);
    scatter_kernel<<<(E_EDGES + 255) / 256, 256>>>(ei);

    // resolve device-global addresses (host side, cached, no graph impact)
    static float *p_mean1 = nullptr, *p_h = nullptr, *p_mean2 = nullptr;
    if (!p_mean1) {
        cudaGetSymbolAddress((void**)&p_mean1, g_mean1);
        cudaGetSymbolAddress((void**)&p_h, g_h);
        cudaGetSymbolAddress((void**)&p_mean2, g_mean2);
    }

    // Layer 1: aggregate x, then h = relu(mean1@Wl1^T + bl1 + x@Wr1^T)
    agg1_kernel<<<(N_NODES * 16 + 255) / 256, 256>>>(x);
    mma_gemm_kernel<64, 1><<<296, 256, SMEM1>>>(p_mean1, x, Wl1, bl1, Wr1, p_h);

    // Layer 2: aggregate h, then out = mean2@Wl2^T + bl2 + h@Wr2^T
    agg2_kernel<<<(N_NODES * 32 + 255) / 256, 256>>>();
    mma_gemm_kernel<128, 0><<<148, 256, SMEM2>>>(p_mean2, p_h, Wl2, bl2, Wr2, out);
}

// round 4
// speedup vs baseline: 1.8476x; 1.2134x over previous
#include <cuda_runtime.h>
#include <cuda_bf16.h>
#include <cstdint>

// Problem constants
#define N_NODES 100000
#define E_EDGES 1600000
#define F_IN 64
#define H_DIM 128

// ---------------- device scratch (no runtime allocation allowed) ----------------
__device__ int   g_cnt[N_NODES];           // in-degree per dst node
__device__ int   g_off[N_NODES];           // CSR offsets (exclusive scan of cnt)
__device__ int   g_cur[N_NODES];           // scatter cursors
__device__ int   g_srcs[E_EDGES];          // src node ids grouped by dst
__device__ int   g_blocksums[128];         // scan partials
__device__ float g_mean1[(size_t)N_NODES * F_IN];   // layer-1 mean aggregate
__device__ float g_h[(size_t)N_NODES * H_DIM];      // layer-1 output (post relu)
__device__ float g_mean2[(size_t)N_NODES * H_DIM];  // layer-2 mean aggregate

// ---------------- CSR build ----------------
__global__ void zero_cnt_kernel() {
    int i = blockIdx.x * blockDim.x + threadIdx.x;
    if (i < N_NODES) g_cnt[i] = 0;
}

// 4 edges per thread (E divisible by 4)
__global__ void count_kernel(const int* __restrict__ ei) {
    int e4 = blockIdx.x * blockDim.x + threadIdx.x;
    if (e4 < E_EDGES / 4) {
        int4 d = ((const int4*)(ei + E_EDGES))[e4];
        atomicAdd(&g_cnt[d.x], 1);
        atomicAdd(&g_cnt[d.y], 1);
        atomicAdd(&g_cnt[d.z], 1);
        atomicAdd(&g_cnt[d.w], 1);
    }
}

// blockDim = 1024; per-block exclusive scan (Hillis-Steele) + block total
__global__ void scan_local_kernel() {
    __shared__ int s[1024];
    int i = blockIdx.x * 1024 + threadIdx.x;
    int v = (i < N_NODES) ? g_cnt[i] : 0;
    s[threadIdx.x] = v;
    __syncthreads();
    for (int d = 1; d < 1024; d <<= 1) {
        int t = (threadIdx.x >= d) ? s[threadIdx.x - d] : 0;
        __syncthreads();
        s[threadIdx.x] += t;
        __syncthreads();
    }
    if (i < N_NODES) g_off[i] = s[threadIdx.x] - v;  // exclusive (local)
    if (threadIdx.x == 1023) g_blocksums[blockIdx.x] = s[1023];
}

// Each block redundantly scans the (<=128) block sums in smem, then adds its
// prefix and writes final offsets + cursors. ALL threads hit EVERY barrier
// (barriers are never under a divergent predicate).
__global__ void scan_finish_kernel(int nblk) {
    __shared__ int bs[128];
    int tid = threadIdx.x;
    int v = 0;
    if (tid < 128) {
        v = (tid < nblk) ? g_blocksums[tid] : 0;
        bs[tid] = v;
    }
    __syncthreads();
    for (int d = 1; d < 128; d <<= 1) {
        int t = (tid < 128 && tid >= d) ? bs[tid - d] : 0;
        __syncthreads();
        if (tid < 128) bs[tid] += t;
        __syncthreads();
    }
    if (tid < 128) bs[tid] -= v;   // inclusive -> exclusive
    __syncthreads();
    int i = blockIdx.x * 1024 + tid;
    if (i < N_NODES) {
        int o = g_off[i] + bs[blockIdx.x];
        g_off[i] = o;
        g_cur[i] = o;
    }
}

__global__ void scatter_kernel(const int* __restrict__ ei) {
    int e4 = blockIdx.x * blockDim.x + threadIdx.x;
    if (e4 < E_EDGES / 4) {
        int4 s = ((const int4*)ei)[e4];
        int4 d = ((const int4*)(ei + E_EDGES))[e4];
        int p0 = atomicAdd(&g_cur[d.x], 1); g_srcs[p0] = s.x;
        int p1 = atomicAdd(&g_cur[d.y], 1); g_srcs[p1] = s.y;
        int p2 = atomicAdd(&g_cur[d.z], 1); g_srcs[p2] = s.z;
        int p3 = atomicAdd(&g_cur[d.w], 1); g_srcs[p3] = s.w;
    }
}

// ---------------- aggregation (mean of src features per dst) ----------------
#define ACC4(a, v) { a.x += v.x; a.y += v.y; a.z += v.z; a.w += v.w; }

// Layer 1: 64 features -> 16 float4 chunks; 16 lanes per node.
__global__ void agg1_kernel(const float* __restrict__ x) {
    int t = blockIdx.x * blockDim.x + threadIdx.x;
    int n = t >> 4;
    int c = t & 15;
    if (n >= N_NODES) return;
    int start = g_off[n];
    int deg = g_cnt[n];
    const float4* x4 = (const float4*)x;
    float4 a0 = make_float4(0.f, 0.f, 0.f, 0.f);
    float4 a1 = a0, a2 = a0, a3 = a0;
    int i = 0;
    for (; i + 8 <= deg; i += 8) {
        int s0 = g_srcs[start + i + 0];
        int s1 = g_srcs[start + i + 1];
        int s2 = g_srcs[start + i + 2];
        int s3 = g_srcs[start + i + 3];
        int s4 = g_srcs[start + i + 4];
        int s5 = g_srcs[start + i + 5];
        int s6 = g_srcs[start + i + 6];
        int s7 = g_srcs[start + i + 7];
        float4 v0 = x4[(size_t)s0 * 16 + c];
        float4 v1 = x4[(size_t)s1 * 16 + c];
        float4 v2 = x4[(size_t)s2 * 16 + c];
        float4 v3 = x4[(size_t)s3 * 16 + c];
        float4 v4 = x4[(size_t)s4 * 16 + c];
        float4 v5 = x4[(size_t)s5 * 16 + c];
        float4 v6 = x4[(size_t)s6 * 16 + c];
        float4 v7 = x4[(size_t)s7 * 16 + c];
        ACC4(a0, v0); ACC4(a1, v1); ACC4(a2, v2); ACC4(a3, v3);
        ACC4(a0, v4); ACC4(a1, v5); ACC4(a2, v6); ACC4(a3, v7);
    }
    for (; i < deg; i++) {
        int s0 = g_srcs[start + i];
        float4 v0 = x4[(size_t)s0 * 16 + c];
        ACC4(a0, v0);
    }
    a0.x += a1.x + a2.x + a3.x;
    a0.y += a1.y + a2.y + a3.y;
    a0.z += a1.z + a2.z + a3.z;
    a0.w += a1.w + a2.w + a3.w;
    float inv = 1.0f / (float)(deg > 0 ? deg : 1);
    float4 r = make_float4(a0.x * inv, a0.y * inv, a0.z * inv, a0.w * inv);
    ((float4*)g_mean1)[(size_t)n * 16 + c] = r;
}

// Layer 2: 128 features -> 32 float4 chunks; full warp per node.
__global__ void agg2_kernel() {
    int t = blockIdx.x * blockDim.x + threadIdx.x;
    int n = t >> 5;
    int c = t & 31;
    if (n >= N_NODES) return;
    int start = g_off[n];
    int deg = g_cnt[n];
    const float4* h4 = (const float4*)g_h;
    float4 a0 = make_float4(0.f, 0.f, 0.f, 0.f);
    float4 a1 = a0, a2 = a0, a3 = a0;
    int i = 0;
    for (; i + 8 <= deg; i += 8) {
        int s0 = g_srcs[start + i + 0];
        int s1 = g_srcs[start + i + 1];
        int s2 = g_srcs[start + i + 2];
        int s3 = g_srcs[start + i + 3];
        int s4 = g_srcs[start + i + 4];
        int s5 = g_srcs[start + i + 5];
        int s6 = g_srcs[start + i + 6];
        int s7 = g_srcs[start + i + 7];
        float4 v0 = h4[(size_t)s0 * 32 + c];
        float4 v1 = h4[(size_t)s1 * 32 + c];
        float4 v2 = h4[(size_t)s2 * 32 + c];
        float4 v3 = h4[(size_t)s3 * 32 + c];
        float4 v4 = h4[(size_t)s4 * 32 + c];
        float4 v5 = h4[(size_t)s5 * 32 + c];
        float4 v6 = h4[(size_t)s6 * 32 + c];
        float4 v7 = h4[(size_t)s7 * 32 + c];
        ACC4(a0, v0); ACC4(a1, v1); ACC4(a2, v2); ACC4(a3, v3);
        ACC4(a0, v4); ACC4(a1, v5); ACC4(a2, v6); ACC4(a3, v7);
    }
    for (; i < deg; i++) {
        int s0 = g_srcs[start + i];
        float4 v0 = h4[(size_t)s0 * 32 + c];
        ACC4(a0, v0);
    }
    a0.x += a1.x + a2.x + a3.x;
    a0.y += a1.y + a2.y + a3.y;
    a0.z += a1.z + a2.z + a3.z;
    a0.w += a1.w + a2.w + a3.w;
    float inv = 1.0f / (float)(deg > 0 ? deg : 1);
    float4 r = make_float4(a0.x * inv, a0.y * inv, a0.z * inv, a0.w * inv);
    ((float4*)g_mean2)[(size_t)n * 32 + c] = r;
}

// ---------------- tf32 tensor-core dual GEMM ----------------
// out[M,128] = [Amean | Aself] @ [Wl ; Wr]^T + bl  (optional relu)
// Block: 256 thr = 8 warps as 2(row) x 4(col); warp tile 64 rows x 32 cols
// (4 mtiles x 4 ntiles of m16n8 -> 4-way register reuse of both fragments).
// B in smem in fragment order; A staged per-64-col chunk, stride-68 rows.

__device__ __forceinline__ unsigned f2tf32(float f) {
    unsigned u;
    asm("cvt.rna.tf32.f32 %0, %1;" : "=r"(u) : "f"(f));
    return u;
}

__device__ __forceinline__ void mma_tf32(float* acc, unsigned a0, unsigned a1,
                                         unsigned a2, unsigned a3,
                                         unsigned b0, unsigned b1) {
    asm volatile(
        "mma.sync.aligned.m16n8k8.row.col.f32.tf32.tf32.f32 "
        "{%0,%1,%2,%3}, {%4,%5,%6,%7}, {%8,%9}, {%0,%1,%2,%3};"
        : "+f"(acc[0]), "+f"(acc[1]), "+f"(acc[2]), "+f"(acc[3])
        : "r"(a0), "r"(a1), "r"(a2), "r"(a3), "r"(b0), "r"(b1));
}

template <int K, int RELU>
__global__ __launch_bounds__(256) void mma_gemm_kernel(
    const float* __restrict__ Amean, const float* __restrict__ Aself,
    const float* __restrict__ Wl, const float* __restrict__ bl,
    const float* __restrict__ Wr, float* __restrict__ out)
{
    constexpr int KK = 2 * K;
    constexpr int NCHUNK = KK / 64;
    constexpr int NFRAG = (KK / 8) * 16;     // ksteps * ntiles
    extern __shared__ unsigned smu[];
    unsigned* Bs = smu;                       // NFRAG * 64
    unsigned* As = smu + NFRAG * 64;          // 128 * 68

    const int tid = threadIdx.x;
    const int lane = tid & 31;
    const int warp = tid >> 5;
    const int wr = warp & 1;                  // row half (0..1): rows wr*64..+64
    const int wc = warp >> 1;                 // col quarter (0..3): cols wc*32..+32
    const int gid = lane >> 2;                // group id (0..7)
    const int tig = lane & 3;                 // thread in group

    // Build B fragments: frag (s, nt) holds k in [8s,8s+8), n in [8nt,8nt+8)
    // layout: Bs[frag*64 + lane*2 + reg]; k = 8s + (l&3) + 4*reg, n = 8nt + (l>>2)
    for (int idx = tid; idx < NFRAG * 64; idx += 256) {
        int frag = idx >> 6;
        int rem = idx & 63;
        int l = rem >> 1;
        int reg = rem & 1;
        int s = frag >> 4;
        int nt = frag & 15;
        int k = s * 8 + (l & 3) + reg * 4;
        int n = nt * 8 + (l >> 2);
        float v = (k < K) ? Wl[n * K + k] : Wr[n * K + (k - K)];
        Bs[idx] = f2tf32(v);
    }

    const int numTiles = (N_NODES + 127) / 128;   // 782
    for (int t = blockIdx.x; t < numTiles; t += gridDim.x) {
        int row0 = t * 128;
        float acc[4][4][4];
#pragma unroll
        for (int mt = 0; mt < 4; mt++)
#pragma unroll
            for (int nt = 0; nt < 4; nt++)
#pragma unroll
                for (int r = 0; r < 4; r++) acc[mt][nt][r] = 0.f;

        for (int c = 0; c < NCHUNK; c++) {
            const float* src = (c * 64 < K) ? Amean : Aself;
            int coff = (c * 64 < K) ? c * 64 : c * 64 - K;
            __syncthreads();
            // stage A chunk [128 rows x 64 cols] as tf32, stride 68
#pragma unroll
            for (int i = 0; i < 8; i++) {
                int f4 = tid + i * 256;
                int r = f4 >> 4;
                int j = f4 & 15;
                float4 v = make_float4(0.f, 0.f, 0.f, 0.f);
                int grow = row0 + r;
                if (grow < N_NODES)
                    v = *(const float4*)(src + (size_t)grow * K + coff + j * 4);
                uint4 u;
                u.x = f2tf32(v.x); u.y = f2tf32(v.y);
                u.z = f2tf32(v.z); u.w = f2tf32(v.w);
                *(uint4*)(As + r * 68 + j * 4) = u;
            }
            __syncthreads();

#pragma unroll
            for (int s = 0; s < 8; s++) {
                // load a-frags for 4 mtiles
                unsigned af[4][4];
#pragma unroll
                for (int mt = 0; mt < 4; mt++) {
                    int r0 = wr * 64 + mt * 16 + gid;
                    af[mt][0] = As[(r0)     * 68 + s * 8 + tig];
                    af[mt][1] = As[(r0 + 8) * 68 + s * 8 + tig];
                    af[mt][2] = As[(r0)     * 68 + s * 8 + tig + 4];
                    af[mt][3] = As[(r0 + 8) * 68 + s * 8 + tig + 4];
                }
                int sg = c * 8 + s;
#pragma unroll
                for (int nt = 0; nt < 4; nt++) {
                    uint2 b = *(const uint2*)(Bs + (sg * 16 + wc * 4 + nt) * 64 + lane * 2);
#pragma unroll
                    for (int mt = 0; mt < 4; mt++)
                        mma_tf32(acc[mt][nt], af[mt][0], af[mt][1], af[mt][2], af[mt][3],
                                 b.x, b.y);
                }
            }
        }

        // epilogue: bias (+relu) + store; warp covers rows [wr*64, wr*64+64),
        // cols [wc*32, wc*32+32)
#pragma unroll
        for (int mt = 0; mt < 4; mt++) {
            int r0 = row0 + wr * 64 + mt * 16 + gid;
            int r1 = r0 + 8;
#pragma unroll
            for (int nt = 0; nt < 4; nt++) {
                int col = wc * 32 + nt * 8 + tig * 2;
                float2 bb = *(const float2*)(bl + col);
                float c0 = acc[mt][nt][0] + bb.x;
                float c1 = acc[mt][nt][1] + bb.y;
                float c2 = acc[mt][nt][2] + bb.x;
                float c3 = acc[mt][nt][3] + bb.y;
                if (RELU) {
                    c0 = fmaxf(c0, 0.f); c1 = fmaxf(c1, 0.f);
                    c2 = fmaxf(c2, 0.f); c3 = fmaxf(c3, 0.f);
                }
                if (r0 < N_NODES)
                    *(float2*)(out + (size_t)r0 * 128 + col) = make_float2(c0, c1);
                if (r1 < N_NODES)
                    *(float2*)(out + (size_t)r1 * 128 + col) = make_float2(c2, c3);
            }
        }
    }
}

// ---------------- launch ----------------
extern "C" void kernel_launch(void* const* d_in, const int* in_sizes, int n_in,
                              void* d_out, int out_size)
{
    const float* x   = (const float*)d_in[0];
    const int*   ei  = (const int*)d_in[1];     // [2, E]: src row then dst row
    const float* Wl1 = (const float*)d_in[2];
    const float* bl1 = (const float*)d_in[3];
    const float* Wr1 = (const float*)d_in[4];
    const float* Wl2 = (const float*)d_in[5];
    const float* bl2 = (const float*)d_in[6];
    const float* Wr2 = (const float*)d_in[7];
    float* out = (float*)d_out;

    const int SMEM1 = (2 * 64 * 128) * 4 + 128 * 68 * 4;    // 100352 B
    const int SMEM2 = (2 * 128 * 128) * 4 + 128 * 68 * 4;   // 165888 B

    static bool attr_done = false;
    if (!attr_done) {
        cudaFuncSetAttribute(mma_gemm_kernel<64, 1>,
                             cudaFuncAttributeMaxDynamicSharedMemorySize, SMEM1);
        cudaFuncSetAttribute(mma_gemm_kernel<128, 0>,
                             cudaFuncAttributeMaxDynamicSharedMemorySize, SMEM2);
        attr_done = true;
    }

    const int NBLK = (N_NODES + 1023) / 1024;   // 98

    // CSR build
    zero_cnt_kernel<<<(N_NODES + 255) / 256, 256>>>();
    count_kernel<<<(E_EDGES / 4 + 255) / 256, 256>>>(ei);
    scan_local_kernel<<<NBLK, 1024>>>();
    scan_finish_kernel<<<NBLK, 1024>>>(NBLK);
    scatter_kernel<<<(E_EDGES / 4 + 255) / 256, 256>>>(ei);

    // resolve device-global addresses (host side, cached, no graph impact)
    static float *p_mean1 = nullptr, *p_h = nullptr, *p_mean2 = nullptr;
    if (!p_mean1) {
        cudaGetSymbolAddress((void**)&p_mean1, g_mean1);
        cudaGetSymbolAddress((void**)&p_h, g_h);
        cudaGetSymbolAddress((void**)&p_mean2, g_mean2);
    }

    // Layer 1: aggregate x, then h = relu(mean1@Wl1^T + bl1 + x@Wr1^T)
    agg1_kernel<<<(N_NODES * 16 + 255) / 256, 256>>>(x);
    mma_gemm_kernel<64, 1><<<296, 256, SMEM1>>>(p_mean1, x, Wl1, bl1, Wr1, p_h);

    // Layer 2: aggregate h, then out = mean2@Wl2^T + bl2 + h@Wr2^T
    agg2_kernel<<<(N_NODES * 32 + 255) / 256, 256>>>();
    mma_gemm_kernel<128, 0><<<148, 256, SMEM2>>>(p_mean2, p_h, Wl2, bl2, Wr2, out);
}

// round 5
// speedup vs baseline: 2.1056x; 1.1397x over previous
#include <cuda_runtime.h>
#include <cuda_bf16.h>
#include <cuda_fp16.h>
#include <cstdint>

// Problem constants
#define N_NODES 100000
#define E_EDGES 1600000
#define F_IN 64
#define H_DIM 128

// ---------------- device scratch (no runtime allocation allowed) ----------------
__device__ int    g_cnt[N_NODES];           // in-degree per dst node
__device__ int    g_off[N_NODES];           // CSR offsets (exclusive scan of cnt)
__device__ int    g_cur[N_NODES];           // scatter cursors
__device__ int    g_srcs[E_EDGES];          // src node ids grouped by dst
__device__ int    g_blocksums[128];         // scan partials
__device__ __half g_x_half[(size_t)N_NODES * F_IN];  // fp16 copy of x
__device__ __half g_h_half[(size_t)N_NODES * H_DIM]; // layer-1 output (fp16, post relu)
__device__ float  g_mean1[(size_t)N_NODES * F_IN];   // layer-1 mean aggregate (fp32)
__device__ float  g_mean2[(size_t)N_NODES * H_DIM];  // layer-2 mean aggregate (fp32)

// ---------------- CSR build ----------------
__global__ void zero_cnt_kernel() {
    int i = blockIdx.x * blockDim.x + threadIdx.x;
    if (i < N_NODES) g_cnt[i] = 0;
}

// 4 edges per thread (E divisible by 4)
__global__ void count_kernel(const int* __restrict__ ei) {
    int e4 = blockIdx.x * blockDim.x + threadIdx.x;
    if (e4 < E_EDGES / 4) {
        int4 d = ((const int4*)(ei + E_EDGES))[e4];
        atomicAdd(&g_cnt[d.x], 1);
        atomicAdd(&g_cnt[d.y], 1);
        atomicAdd(&g_cnt[d.z], 1);
        atomicAdd(&g_cnt[d.w], 1);
    }
}

// blockDim = 1024; per-block exclusive scan (Hillis-Steele) + block total
__global__ void scan_local_kernel() {
    __shared__ int s[1024];
    int i = blockIdx.x * 1024 + threadIdx.x;
    int v = (i < N_NODES) ? g_cnt[i] : 0;
    s[threadIdx.x] = v;
    __syncthreads();
    for (int d = 1; d < 1024; d <<= 1) {
        int t = (threadIdx.x >= d) ? s[threadIdx.x - d] : 0;
        __syncthreads();
        s[threadIdx.x] += t;
        __syncthreads();
    }
    if (i < N_NODES) g_off[i] = s[threadIdx.x] - v;  // exclusive (local)
    if (threadIdx.x == 1023) g_blocksums[blockIdx.x] = s[1023];
}

// Each block redundantly scans the (<=128) block sums in smem, then adds its
// prefix and writes final offsets + cursors. ALL threads hit EVERY barrier.
__global__ void scan_finish_kernel(int nblk) {
    __shared__ int bs[128];
    int tid = threadIdx.x;
    int v = 0;
    if (tid < 128) {
        v = (tid < nblk) ? g_blocksums[tid] : 0;
        bs[tid] = v;
    }
    __syncthreads();
    for (int d = 1; d < 128; d <<= 1) {
        int t = (tid < 128 && tid >= d) ? bs[tid - d] : 0;
        __syncthreads();
        if (tid < 128) bs[tid] += t;
        __syncthreads();
    }
    if (tid < 128) bs[tid] -= v;   // inclusive -> exclusive
    __syncthreads();
    int i = blockIdx.x * 1024 + tid;
    if (i < N_NODES) {
        int o = g_off[i] + bs[blockIdx.x];
        g_off[i] = o;
        g_cur[i] = o;
    }
}

__global__ void scatter_kernel(const int* __restrict__ ei) {
    int e4 = blockIdx.x * blockDim.x + threadIdx.x;
    if (e4 < E_EDGES / 4) {
        int4 s = ((const int4*)ei)[e4];
        int4 d = ((const int4*)(ei + E_EDGES))[e4];
        int p0 = atomicAdd(&g_cur[d.x], 1); g_srcs[p0] = s.x;
        int p1 = atomicAdd(&g_cur[d.y], 1); g_srcs[p1] = s.y;
        int p2 = atomicAdd(&g_cur[d.z], 1); g_srcs[p2] = s.z;
        int p3 = atomicAdd(&g_cur[d.w], 1); g_srcs[p3] = s.w;
    }
}

// ---------------- x -> fp16 conversion ----------------
// one uint4 (8 halves) per thread
__global__ void x2half_kernel(const float* __restrict__ x) {
    int i = blockIdx.x * blockDim.x + threadIdx.x;
    if (i < N_NODES * (F_IN / 8)) {
        float4 f0 = ((const float4*)x)[i * 2 + 0];
        float4 f1 = ((const float4*)x)[i * 2 + 1];
        __half2 h0 = __floats2half2_rn(f0.x, f0.y);
        __half2 h1 = __floats2half2_rn(f0.z, f0.w);
        __half2 h2 = __floats2half2_rn(f1.x, f1.y);
        __half2 h3 = __floats2half2_rn(f1.z, f1.w);
        uint4 u;
        u.x = *(unsigned*)&h0; u.y = *(unsigned*)&h1;
        u.z = *(unsigned*)&h2; u.w = *(unsigned*)&h3;
        ((uint4*)g_x_half)[i] = u;
    }
}

// ---------------- aggregation (mean of src fp16 features per dst, fp32 acc) --
__device__ __forceinline__ void acc_u4(float* a, uint4 u) {
    float2 f0 = __half22float2(*(__half2*)&u.x);
    float2 f1 = __half22float2(*(__half2*)&u.y);
    float2 f2 = __half22float2(*(__half2*)&u.z);
    float2 f3 = __half22float2(*(__half2*)&u.w);
    a[0] += f0.x; a[1] += f0.y; a[2] += f1.x; a[3] += f1.y;
    a[4] += f2.x; a[5] += f2.y; a[6] += f3.x; a[7] += f3.y;
}

// LPN lanes per node, each lane owns 8 contiguous cols (one uint4 of halves).
// ROW_U4 = row stride in uint4 (= feature_dim/8). MEAN has feature_dim cols.
template <int LPN_LOG, int ROW_U4>
__device__ __forceinline__ void agg_body(const __half* __restrict__ feat,
                                         float* __restrict__ mean) {
    int t = blockIdx.x * blockDim.x + threadIdx.x;
    int n = t >> LPN_LOG;
    int c = t & ((1 << LPN_LOG) - 1);
    if (n >= N_NODES) return;
    int start = g_off[n];
    int deg = g_cnt[n];
    const uint4* f4 = (const uint4*)feat;
    float a[8];
#pragma unroll
    for (int j = 0; j < 8; j++) a[j] = 0.f;
    int i = 0;
    for (; i + 8 <= deg; i += 8) {
        int s0 = g_srcs[start + i + 0];
        int s1 = g_srcs[start + i + 1];
        int s2 = g_srcs[start + i + 2];
        int s3 = g_srcs[start + i + 3];
        int s4 = g_srcs[start + i + 4];
        int s5 = g_srcs[start + i + 5];
        int s6 = g_srcs[start + i + 6];
        int s7 = g_srcs[start + i + 7];
        uint4 v0 = f4[(size_t)s0 * ROW_U4 + c];
        uint4 v1 = f4[(size_t)s1 * ROW_U4 + c];
        uint4 v2 = f4[(size_t)s2 * ROW_U4 + c];
        uint4 v3 = f4[(size_t)s3 * ROW_U4 + c];
        uint4 v4 = f4[(size_t)s4 * ROW_U4 + c];
        uint4 v5 = f4[(size_t)s5 * ROW_U4 + c];
        uint4 v6 = f4[(size_t)s6 * ROW_U4 + c];
        uint4 v7 = f4[(size_t)s7 * ROW_U4 + c];
        acc_u4(a, v0); acc_u4(a, v1); acc_u4(a, v2); acc_u4(a, v3);
        acc_u4(a, v4); acc_u4(a, v5); acc_u4(a, v6); acc_u4(a, v7);
    }
    for (; i < deg; i++) {
        int s0 = g_srcs[start + i];
        acc_u4(a, f4[(size_t)s0 * ROW_U4 + c]);
    }
    float inv = 1.0f / (float)(deg > 0 ? deg : 1);
    float4 r0 = make_float4(a[0] * inv, a[1] * inv, a[2] * inv, a[3] * inv);
    float4 r1 = make_float4(a[4] * inv, a[5] * inv, a[6] * inv, a[7] * inv);
    float4* m4 = (float4*)(mean + (size_t)n * (ROW_U4 * 8) + c * 8);
    m4[0] = r0;
    m4[1] = r1;
}

__global__ void agg1_kernel() { agg_body<3, 8>(g_x_half, g_mean1); }    // 64 cols, 8 lanes/node
__global__ void agg2_kernel() { agg_body<4, 16>(g_h_half, g_mean2); }   // 128 cols, 16 lanes/node

// ---------------- tf32 tensor-core dual GEMM ----------------
// out[M,128] = [Amean | Aself] @ [Wl ; Wr]^T + bl  (optional relu)
// Amean fp32, Aself fp16. Block: 256 thr = 8 warps as 2(row) x 4(col);
// warp tile 64 rows x 32 cols. B in smem in fragment order; A staged per-64-col
// chunk (tf32), stride-68 rows (conflict-free a-frag LDS).

__device__ __forceinline__ unsigned f2tf32(float f) {
    unsigned u;
    asm("cvt.rna.tf32.f32 %0, %1;" : "=r"(u) : "f"(f));
    return u;
}

__device__ __forceinline__ void mma_tf32(float* acc, unsigned a0, unsigned a1,
                                         unsigned a2, unsigned a3,
                                         unsigned b0, unsigned b1) {
    asm volatile(
        "mma.sync.aligned.m16n8k8.row.col.f32.tf32.tf32.f32 "
        "{%0,%1,%2,%3}, {%4,%5,%6,%7}, {%8,%9}, {%0,%1,%2,%3};"
        : "+f"(acc[0]), "+f"(acc[1]), "+f"(acc[2]), "+f"(acc[3])
        : "r"(a0), "r"(a1), "r"(a2), "r"(a3), "r"(b0), "r"(b1));
}

template <int K, int RELU, int OUT_HALF>
__global__ __launch_bounds__(256) void mma_gemm_kernel(
    const float* __restrict__ Amean, const __half* __restrict__ Aself,
    const float* __restrict__ Wl, const float* __restrict__ bl,
    const float* __restrict__ Wr, void* __restrict__ out_v)
{
    constexpr int KK = 2 * K;
    constexpr int NCHUNK = KK / 64;
    constexpr int NFRAG = (KK / 8) * 16;     // ksteps * ntiles
    extern __shared__ unsigned smu[];
    unsigned* Bs = smu;                       // NFRAG * 64
    unsigned* As = smu + NFRAG * 64;          // 128 * 68

    const int tid = threadIdx.x;
    const int lane = tid & 31;
    const int warp = tid >> 5;
    const int wr = warp & 1;                  // row half
    const int wc = warp >> 1;                 // col quarter
    const int gid = lane >> 2;
    const int tig = lane & 3;

    // Build B fragments: frag (s, nt): k in [8s,8s+8), n in [8nt,8nt+8)
    for (int idx = tid; idx < NFRAG * 64; idx += 256) {
        int frag = idx >> 6;
        int rem = idx & 63;
        int l = rem >> 1;
        int reg = rem & 1;
        int s = frag >> 4;
        int nt = frag & 15;
        int k = s * 8 + (l & 3) + reg * 4;
        int n = nt * 8 + (l >> 2);
        float v = (k < K) ? Wl[n * K + k] : Wr[n * K + (k - K)];
        Bs[idx] = f2tf32(v);
    }

    const int numTiles = (N_NODES + 127) / 128;   // 782
    for (int t = blockIdx.x; t < numTiles; t += gridDim.x) {
        int row0 = t * 128;
        float acc[4][4][4];
#pragma unroll
        for (int mt = 0; mt < 4; mt++)
#pragma unroll
            for (int nt = 0; nt < 4; nt++)
#pragma unroll
                for (int r = 0; r < 4; r++) acc[mt][nt][r] = 0.f;

        for (int c = 0; c < NCHUNK; c++) {
            bool isMean = (c * 64 < K);
            __syncthreads();
            if (isMean) {
                // fp32 chunk: 16 float4 per row
                int coff = c * 64;
#pragma unroll
                for (int i = 0; i < 8; i++) {
                    int f4 = tid + i * 256;
                    int r = f4 >> 4;
                    int j = f4 & 15;
                    float4 v = make_float4(0.f, 0.f, 0.f, 0.f);
                    int grow = row0 + r;
                    if (grow < N_NODES)
                        v = *(const float4*)(Amean + (size_t)grow * K + coff + j * 4);
                    uint4 u;
                    u.x = f2tf32(v.x); u.y = f2tf32(v.y);
                    u.z = f2tf32(v.z); u.w = f2tf32(v.w);
                    *(uint4*)(As + r * 68 + j * 4) = u;
                }
            } else {
                // fp16 chunk: 8 uint4 (of halves) per row
                int coff = c * 64 - K;
#pragma unroll
                for (int i = 0; i < 4; i++) {
                    int q = tid + i * 256;
                    int r = q >> 3;
                    int j = q & 7;
                    uint4 u = make_uint4(0, 0, 0, 0);
                    int grow = row0 + r;
                    if (grow < N_NODES)
                        u = *(const uint4*)(Aself + (size_t)grow * K + coff + j * 8);
                    float2 f0 = __half22float2(*(__half2*)&u.x);
                    float2 f1 = __half22float2(*(__half2*)&u.y);
                    float2 f2 = __half22float2(*(__half2*)&u.z);
                    float2 f3 = __half22float2(*(__half2*)&u.w);
                    uint4 t0, t1;
                    t0.x = f2tf32(f0.x); t0.y = f2tf32(f0.y);
                    t0.z = f2tf32(f1.x); t0.w = f2tf32(f1.y);
                    t1.x = f2tf32(f2.x); t1.y = f2tf32(f2.y);
                    t1.z = f2tf32(f3.x); t1.w = f2tf32(f3.y);
                    *(uint4*)(As + r * 68 + j * 8) = t0;
                    *(uint4*)(As + r * 68 + j * 8 + 4) = t1;
                }
            }
            __syncthreads();

#pragma unroll
            for (int s = 0; s < 8; s++) {
                unsigned af[4][4];
#pragma unroll
                for (int mt = 0; mt < 4; mt++) {
                    int r0 = wr * 64 + mt * 16 + gid;
                    af[mt][0] = As[(r0)     * 68 + s * 8 + tig];
                    af[mt][1] = As[(r0 + 8) * 68 + s * 8 + tig];
                    af[mt][2] = As[(r0)     * 68 + s * 8 + tig + 4];
                    af[mt][3] = As[(r0 + 8) * 68 + s * 8 + tig + 4];
                }
                int sg = c * 8 + s;
#pragma unroll
                for (int nt = 0; nt < 4; nt++) {
                    uint2 b = *(const uint2*)(Bs + (sg * 16 + wc * 4 + nt) * 64 + lane * 2);
#pragma unroll
                    for (int mt = 0; mt < 4; mt++)
                        mma_tf32(acc[mt][nt], af[mt][0], af[mt][1], af[mt][2], af[mt][3],
                                 b.x, b.y);
                }
            }
        }

        // epilogue: bias (+relu) + store
#pragma unroll
        for (int mt = 0; mt < 4; mt++) {
            int r0 = row0 + wr * 64 + mt * 16 + gid;
            int r1 = r0 + 8;
#pragma unroll
            for (int nt = 0; nt < 4; nt++) {
                int col = wc * 32 + nt * 8 + tig * 2;
                float2 bb = *(const float2*)(bl + col);
                float c0 = acc[mt][nt][0] + bb.x;
                float c1 = acc[mt][nt][1] + bb.y;
                float c2 = acc[mt][nt][2] + bb.x;
                float c3 = acc[mt][nt][3] + bb.y;
                if (RELU) {
                    c0 = fmaxf(c0, 0.f); c1 = fmaxf(c1, 0.f);
                    c2 = fmaxf(c2, 0.f); c3 = fmaxf(c3, 0.f);
                }
                if (OUT_HALF) {
                    __half* o = (__half*)out_v;
                    __half2 p0 = __floats2half2_rn(c0, c1);
                    __half2 p1 = __floats2half2_rn(c2, c3);
                    if (r0 < N_NODES) *(__half2*)(o + (size_t)r0 * 128 + col) = p0;
                    if (r1 < N_NODES) *(__half2*)(o + (size_t)r1 * 128 + col) = p1;
                } else {
                    float* o = (float*)out_v;
                    if (r0 < N_NODES)
                        *(float2*)(o + (size_t)r0 * 128 + col) = make_float2(c0, c1);
                    if (r1 < N_NODES)
                        *(float2*)(o + (size_t)r1 * 128 + col) = make_float2(c2, c3);
                }
            }
        }
    }
}

// ---------------- launch ----------------
extern "C" void kernel_launch(void* const* d_in, const int* in_sizes, int n_in,
                              void* d_out, int out_size)
{
    const float* x   = (const float*)d_in[0];
    const int*   ei  = (const int*)d_in[1];     // [2, E]: src row then dst row
    const float* Wl1 = (const float*)d_in[2];
    const float* bl1 = (const float*)d_in[3];
    const float* Wr1 = (const float*)d_in[4];
    const float* Wl2 = (const float*)d_in[5];
    const float* bl2 = (const float*)d_in[6];
    const float* Wr2 = (const float*)d_in[7];
    float* out = (float*)d_out;

    const int SMEM1 = (2 * 64 * 128) * 4 + 128 * 68 * 4;    // 100352 B
    const int SMEM2 = (2 * 128 * 128) * 4 + 128 * 68 * 4;   // 165888 B

    static bool attr_done = false;
    if (!attr_done) {
        cudaFuncSetAttribute(mma_gemm_kernel<64, 1, 1>,
                             cudaFuncAttributeMaxDynamicSharedMemorySize, SMEM1);
        cudaFuncSetAttribute(mma_gemm_kernel<128, 0, 0>,
                             cudaFuncAttributeMaxDynamicSharedMemorySize, SMEM2);
        attr_done = true;
    }

    const int NBLK = (N_NODES + 1023) / 1024;   // 98

    // CSR build + x conversion
    zero_cnt_kernel<<<(N_NODES + 255) / 256, 256>>>();
    count_kernel<<<(E_EDGES / 4 + 255) / 256, 256>>>(ei);
    x2half_kernel<<<(N_NODES * (F_IN / 8) + 255) / 256, 256>>>(x);
    scan_local_kernel<<<NBLK, 1024>>>();
    scan_finish_kernel<<<NBLK, 1024>>>(NBLK);
    scatter_kernel<<<(E_EDGES / 4 + 255) / 256, 256>>>(ei);

    // resolve device-global addresses (host side, cached, no graph impact)
    static float *p_mean1 = nullptr, *p_mean2 = nullptr;
    static __half *p_xh = nullptr, *p_hh = nullptr;
    if (!p_mean1) {
        cudaGetSymbolAddress((void**)&p_mean1, g_mean1);
        cudaGetSymbolAddress((void**)&p_mean2, g_mean2);
        cudaGetSymbolAddress((void**)&p_xh, g_x_half);
        cudaGetSymbolAddress((void**)&p_hh, g_h_half);
    }

    // Layer 1: aggregate x (fp16), then h = relu(mean1@Wl1^T + bl1 + x@Wr1^T) -> fp16
    agg1_kernel<<<(N_NODES * 8 + 255) / 256, 256>>>();
    mma_gemm_kernel<64, 1, 1><<<296, 256, SMEM1>>>(p_mean1, p_xh, Wl1, bl1, Wr1, p_hh);

    // Layer 2: aggregate h (fp16), then out = mean2@Wl2^T + bl2 + h@Wr2^T (fp32)
    agg2_kernel<<<(N_NODES * 16 + 255) / 256, 256>>>();
    mma_gemm_kernel<128, 0, 0><<<148, 256, SMEM2>>>(p_mean2, p_hh, Wl2, bl2, Wr2, out);
}

// round 8
// speedup vs baseline: 2.5420x; 1.2072x over previous
#include <cuda_runtime.h>
#include <cuda_bf16.h>
#include <cuda_fp16.h>
#include <cstdint>

// Problem constants
#define N_NODES 100000
#define E_EDGES 1600000
#define F_IN 64
#define H_DIM 128

// ---------------- device scratch (no runtime allocation allowed) ----------------
__device__ int    g_cnt[N_NODES];
__device__ int    g_off[N_NODES];
__device__ int    g_cur[N_NODES];
__device__ int    g_srcs[E_EDGES];
__device__ int    g_blocksums[128];
__device__ __half g_x_half[(size_t)N_NODES * F_IN];
__device__ __half g_h_half[(size_t)N_NODES * H_DIM];
__device__ float  g_mean1[(size_t)N_NODES * F_IN];
__device__ float  g_mean2[(size_t)N_NODES * H_DIM];

// ---------------- prep: zero counters + convert x -> fp16 ----------------
__global__ void prep_kernel(const float* __restrict__ x) {
    int i = blockIdx.x * blockDim.x + threadIdx.x;
    if (i < N_NODES) g_cnt[i] = 0;
    if (i < N_NODES * (F_IN / 8)) {
        float4 f0 = ((const float4*)x)[i * 2 + 0];
        float4 f1 = ((const float4*)x)[i * 2 + 1];
        __half2 h0 = __floats2half2_rn(f0.x, f0.y);
        __half2 h1 = __floats2half2_rn(f0.z, f0.w);
        __half2 h2 = __floats2half2_rn(f1.x, f1.y);
        __half2 h3 = __floats2half2_rn(f1.z, f1.w);
        uint4 u;
        u.x = *(unsigned*)&h0; u.y = *(unsigned*)&h1;
        u.z = *(unsigned*)&h2; u.w = *(unsigned*)&h3;
        ((uint4*)g_x_half)[i] = u;
    }
}

// ---------------- CSR build ----------------
__global__ void count_kernel(const int* __restrict__ ei) {
    int e4 = blockIdx.x * blockDim.x + threadIdx.x;
    if (e4 < E_EDGES / 4) {
        int4 d = ((const int4*)(ei + E_EDGES))[e4];
        atomicAdd(&g_cnt[d.x], 1);
        atomicAdd(&g_cnt[d.y], 1);
        atomicAdd(&g_cnt[d.z], 1);
        atomicAdd(&g_cnt[d.w], 1);
    }
}

__global__ void scan_local_kernel() {
    __shared__ int s[1024];
    int i = blockIdx.x * 1024 + threadIdx.x;
    int v = (i < N_NODES) ? g_cnt[i] : 0;
    s[threadIdx.x] = v;
    __syncthreads();
    for (int d = 1; d < 1024; d <<= 1) {
        int t = (threadIdx.x >= d) ? s[threadIdx.x - d] : 0;
        __syncthreads();
        s[threadIdx.x] += t;
        __syncthreads();
    }
    if (i < N_NODES) g_off[i] = s[threadIdx.x] - v;
    if (threadIdx.x == 1023) g_blocksums[blockIdx.x] = s[1023];
}

// ALL threads hit EVERY barrier (no divergent barriers).
__global__ void scan_finish_kernel(int nblk) {
    __shared__ int bs[128];
    int tid = threadIdx.x;
    int v = 0;
    if (tid < 128) {
        v = (tid < nblk) ? g_blocksums[tid] : 0;
        bs[tid] = v;
    }
    __syncthreads();
    for (int d = 1; d < 128; d <<= 1) {
        int t = (tid < 128 && tid >= d) ? bs[tid - d] : 0;
        __syncthreads();
        if (tid < 128) bs[tid] += t;
        __syncthreads();
    }
    if (tid < 128) bs[tid] -= v;
    __syncthreads();
    int i = blockIdx.x * 1024 + tid;
    if (i < N_NODES) {
        int o = g_off[i] + bs[blockIdx.x];
        g_off[i] = o;
        g_cur[i] = o;
    }
}

__global__ void scatter_kernel(const int* __restrict__ ei) {
    int e4 = blockIdx.x * blockDim.x + threadIdx.x;
    if (e4 < E_EDGES / 4) {
        int4 s = ((const int4*)ei)[e4];
        int4 d = ((const int4*)(ei + E_EDGES))[e4];
        int p0 = atomicAdd(&g_cur[d.x], 1); g_srcs[p0] = s.x;
        int p1 = atomicAdd(&g_cur[d.y], 1); g_srcs[p1] = s.y;
        int p2 = atomicAdd(&g_cur[d.z], 1); g_srcs[p2] = s.z;
        int p3 = atomicAdd(&g_cur[d.w], 1); g_srcs[p3] = s.w;
    }
}

// ---------------- aggregation (mean of src fp16 features, fp32 acc) ----------
__device__ __forceinline__ void acc_u4(float* a, uint4 u) {
    float2 f0 = __half22float2(*(__half2*)&u.x);
    float2 f1 = __half22float2(*(__half2*)&u.y);
    float2 f2 = __half22float2(*(__half2*)&u.z);
    float2 f3 = __half22float2(*(__half2*)&u.w);
    a[0] += f0.x; a[1] += f0.y; a[2] += f1.x; a[3] += f1.y;
    a[4] += f2.x; a[5] += f2.y; a[6] += f3.x; a[7] += f3.y;
}

// Grid-stride over nodes per lane-group: per-group work averages over ~several
// nodes (sum of Poissons) instead of warp-max over single nodes.
template <int LPN_LOG, int ROW_U4>
__device__ __forceinline__ void agg_body(const __half* __restrict__ feat,
                                         float* __restrict__ mean) {
    int t = blockIdx.x * blockDim.x + threadIdx.x;
    int g0 = t >> LPN_LOG;
    int ngroups = (gridDim.x * blockDim.x) >> LPN_LOG;
    int c = t & ((1 << LPN_LOG) - 1);
    const uint4* f4 = (const uint4*)feat;
    for (int n = g0; n < N_NODES; n += ngroups) {
        int start = g_off[n];
        int deg = g_cnt[n];
        float a[8];
#pragma unroll
        for (int j = 0; j < 8; j++) a[j] = 0.f;
        int i = 0;
        for (; i + 8 <= deg; i += 8) {
            int s0 = g_srcs[start + i + 0];
            int s1 = g_srcs[start + i + 1];
            int s2 = g_srcs[start + i + 2];
            int s3 = g_srcs[start + i + 3];
            int s4 = g_srcs[start + i + 4];
            int s5 = g_srcs[start + i + 5];
            int s6 = g_srcs[start + i + 6];
            int s7 = g_srcs[start + i + 7];
            uint4 v0 = f4[(size_t)s0 * ROW_U4 + c];
            uint4 v1 = f4[(size_t)s1 * ROW_U4 + c];
            uint4 v2 = f4[(size_t)s2 * ROW_U4 + c];
            uint4 v3 = f4[(size_t)s3 * ROW_U4 + c];
            uint4 v4 = f4[(size_t)s4 * ROW_U4 + c];
            uint4 v5 = f4[(size_t)s5 * ROW_U4 + c];
            uint4 v6 = f4[(size_t)s6 * ROW_U4 + c];
            uint4 v7 = f4[(size_t)s7 * ROW_U4 + c];
            acc_u4(a, v0); acc_u4(a, v1); acc_u4(a, v2); acc_u4(a, v3);
            acc_u4(a, v4); acc_u4(a, v5); acc_u4(a, v6); acc_u4(a, v7);
        }
        for (; i < deg; i++) {
            int s0 = g_srcs[start + i];
            acc_u4(a, f4[(size_t)s0 * ROW_U4 + c]);
        }
        float inv = 1.0f / (float)(deg > 0 ? deg : 1);
        float4 r0 = make_float4(a[0] * inv, a[1] * inv, a[2] * inv, a[3] * inv);
        float4 r1 = make_float4(a[4] * inv, a[5] * inv, a[6] * inv, a[7] * inv);
        float4* m4 = (float4*)(mean + (size_t)n * (ROW_U4 * 8) + c * 8);
        m4[0] = r0;
        m4[1] = r1;
    }
}

__global__ void agg1_kernel() { agg_body<3, 8>(g_x_half, g_mean1); }
__global__ void agg2_kernel() { agg_body<4, 16>(g_h_half, g_mean2); }

// ---------------- fp16 tensor-core dual GEMM (m16n8k16) ----------------
// out[M,128] = [Amean | Aself] @ [Wl ; Wr]^T + bl  (optional relu)
// Amean fp32 (converted to fp16 on staging), Aself fp16.
// Block: 256 thr = 8 warps as 2(row) x 4(col); warp tile 64x32
// (4 mtiles x 4 ntiles). B in smem in k16-fragment order (half2 packed);
// A staged per-64-col chunk as fp16, row stride 36 u32 (conflict-free).

__device__ __forceinline__ void mma_f16(float* acc, unsigned a0, unsigned a1,
                                        unsigned a2, unsigned a3,
                                        unsigned b0, unsigned b1) {
    asm volatile(
        "mma.sync.aligned.m16n8k16.row.col.f32.f16.f16.f32 "
        "{%0,%1,%2,%3}, {%4,%5,%6,%7}, {%8,%9}, {%0,%1,%2,%3};"
        : "+f"(acc[0]), "+f"(acc[1]), "+f"(acc[2]), "+f"(acc[3])
        : "r"(a0), "r"(a1), "r"(a2), "r"(a3), "r"(b0), "r"(b1));
}

template <int K, int RELU, int OUT_HALF>
__global__ __launch_bounds__(256) void mma_gemm_kernel(
    const float* __restrict__ Amean, const __half* __restrict__ Aself,
    const float* __restrict__ Wl, const float* __restrict__ bl,
    const float* __restrict__ Wr, void* __restrict__ out_v)
{
    constexpr int KK = 2 * K;
    constexpr int NCHUNK = KK / 64;          // 64-col staging chunks
    constexpr int NKS = KK / 16;             // k16 steps total
    constexpr int NFRAG = NKS * 16;          // frags (kstep, ntile)
    extern __shared__ unsigned smu[];
    unsigned* Bs = smu;                       // NFRAG * 64 u32 (half2 pairs)
    unsigned* As = smu + NFRAG * 64;          // 128 rows * 36 u32 (fp16)

    const int tid = threadIdx.x;
    const int lane = tid & 31;
    const int warp = tid >> 5;
    const int wr = warp & 1;
    const int wc = warp >> 1;
    const int gid = lane >> 2;
    const int tig = lane & 3;

    // Build B fragments (half2 packed):
    // Bs[frag*64 + l*2 + reg]: n = nt*8 + (l>>2), k = s*16 + (l&3)*2 + reg*8 (+0,+1)
    for (int idx = tid; idx < NFRAG * 64; idx += 256) {
        int frag = idx >> 6;
        int rem = idx & 63;
        int l = rem >> 1;
        int reg = rem & 1;
        int s = frag >> 4;
        int nt = frag & 15;
        int n = nt * 8 + (l >> 2);
        int k0 = s * 16 + (l & 3) * 2 + reg * 8;
        float v0, v1;
        if (k0 < K) { v0 = Wl[n * K + k0]; v1 = Wl[n * K + k0 + 1]; }
        else        { v0 = Wr[n * K + k0 - K]; v1 = Wr[n * K + k0 - K + 1]; }
        __half2 h = __floats2half2_rn(v0, v1);
        Bs[idx] = *(unsigned*)&h;
    }

    const int numTiles = (N_NODES + 127) / 128;   // 782
    for (int t = blockIdx.x; t < numTiles; t += gridDim.x) {
        int row0 = t * 128;
        float acc[4][4][4];
#pragma unroll
        for (int mt = 0; mt < 4; mt++)
#pragma unroll
            for (int nt = 0; nt < 4; nt++)
#pragma unroll
                for (int r = 0; r < 4; r++) acc[mt][nt][r] = 0.f;

        for (int c = 0; c < NCHUNK; c++) {
            bool isMean = (c * 64 < K);
            __syncthreads();
            // stage 128 rows x 64 cols as fp16; item = (row, 8-col group)
#pragma unroll
            for (int i = 0; i < 4; i++) {
                int item = tid + i * 256;
                int r = item >> 3;
                int j = item & 7;
                int grow = row0 + r;
                uint4 u = make_uint4(0, 0, 0, 0);
                if (grow < N_NODES) {
                    if (isMean) {
                        int coff = c * 64;
                        const float* p = Amean + (size_t)grow * K + coff + j * 8;
                        float4 v0 = *(const float4*)p;
                        float4 v1 = *(const float4*)(p + 4);
                        __half2 h0 = __floats2half2_rn(v0.x, v0.y);
                        __half2 h1 = __floats2half2_rn(v0.z, v0.w);
                        __half2 h2 = __floats2half2_rn(v1.x, v1.y);
                        __half2 h3 = __floats2half2_rn(v1.z, v1.w);
                        u.x = *(unsigned*)&h0; u.y = *(unsigned*)&h1;
                        u.z = *(unsigned*)&h2; u.w = *(unsigned*)&h3;
                    } else {
                        int coff = c * 64 - K;
                        u = *(const uint4*)(Aself + (size_t)grow * K + coff + j * 8);
                    }
                }
                *(uint4*)(As + r * 36 + j * 4) = u;
            }
            __syncthreads();

#pragma unroll
            for (int s = 0; s < 4; s++) {            // 4 k16 steps per chunk
                unsigned af[4][4];
#pragma unroll
                for (int mt = 0; mt < 4; mt++) {
                    int r0 = wr * 64 + mt * 16 + gid;
                    af[mt][0] = As[(r0)     * 36 + s * 8 + tig];
                    af[mt][1] = As[(r0 + 8) * 36 + s * 8 + tig];
                    af[mt][2] = As[(r0)     * 36 + s * 8 + tig + 4];
                    af[mt][3] = As[(r0 + 8) * 36 + s * 8 + tig + 4];
                }
                int sg = c * 4 + s;
#pragma unroll
                for (int nt = 0; nt < 4; nt++) {
                    uint2 b = *(const uint2*)(Bs + (sg * 16 + wc * 4 + nt) * 64 + lane * 2);
#pragma unroll
                    for (int mt = 0; mt < 4; mt++)
                        mma_f16(acc[mt][nt], af[mt][0], af[mt][1], af[mt][2], af[mt][3],
                                b.x, b.y);
                }
            }
        }

        // epilogue: bias (+relu) + store
#pragma unroll
        for (int mt = 0; mt < 4; mt++) {
            int r0 = row0 + wr * 64 + mt * 16 + gid;
            int r1 = r0 + 8;
#pragma unroll
            for (int nt = 0; nt < 4; nt++) {
                int col = wc * 32 + nt * 8 + tig * 2;
                float2 bb = *(const float2*)(bl + col);
                float c0 = acc[mt][nt][0] + bb.x;
                float c1 = acc[mt][nt][1] + bb.y;
                float c2 = acc[mt][nt][2] + bb.x;
                float c3 = acc[mt][nt][3] + bb.y;
                if (RELU) {
                    c0 = fmaxf(c0, 0.f); c1 = fmaxf(c1, 0.f);
                    c2 = fmaxf(c2, 0.f); c3 = fmaxf(c3, 0.f);
                }
                if (OUT_HALF) {
                    __half* o = (__half*)out_v;
                    __half2 p0 = __floats2half2_rn(c0, c1);
                    __half2 p1 = __floats2half2_rn(c2, c3);
                    if (r0 < N_NODES) *(__half2*)(o + (size_t)r0 * 128 + col) = p0;
                    if (r1 < N_NODES) *(__half2*)(o + (size_t)r1 * 128 + col) = p1;
                } else {
                    float* o = (float*)out_v;
                    if (r0 < N_NODES)
                        *(float2*)(o + (size_t)r0 * 128 + col) = make_float2(c0, c1);
                    if (r1 < N_NODES)
                        *(float2*)(o + (size_t)r1 * 128 + col) = make_float2(c2, c3);
                }
            }
        }
    }
}

// ---------------- launch ----------------
extern "C" void kernel_launch(void* const* d_in, const int* in_sizes, int n_in,
                              void* d_out, int out_size)
{
    const float* x   = (const float*)d_in[0];
    const int*   ei  = (const int*)d_in[1];
    const float* Wl1 = (const float*)d_in[2];
    const float* bl1 = (const float*)d_in[3];
    const float* Wr1 = (const float*)d_in[4];
    const float* Wl2 = (const float*)d_in[5];
    const float* bl2 = (const float*)d_in[6];
    const float* Wr2 = (const float*)d_in[7];
    float* out = (float*)d_out;

    // smem: Bs = (2K/16)*16*64 u32, As = 128*36 u32
    const int SMEM1 = (8 * 16 * 64) * 4 + 128 * 36 * 4;    // 32768+18432 = 51200 B
    const int SMEM2 = (16 * 16 * 64) * 4 + 128 * 36 * 4;   // 65536+18432 = 83968 B

    static bool attr_done = false;
    if (!attr_done) {
        cudaFuncSetAttribute(mma_gemm_kernel<64, 1, 1>,
                             cudaFuncAttributeMaxDynamicSharedMemorySize, SMEM1);
        cudaFuncSetAttribute(mma_gemm_kernel<128, 0, 0>,
                             cudaFuncAttributeMaxDynamicSharedMemorySize, SMEM2);
        attr_done = true;
    }

    const int NBLK = (N_NODES + 1023) / 1024;   // 98

    // prep (zero counters + x->fp16), then CSR build
    prep_kernel<<<(N_NODES * (F_IN / 8) + 255) / 256, 256>>>(x);
    count_kernel<<<(E_EDGES / 4 + 255) / 256, 256>>>(ei);
    scan_local_kernel<<<NBLK, 1024>>>();
    scan_finish_kernel<<<NBLK, 1024>>>(NBLK);
    scatter_kernel<<<(E_EDGES / 4 + 255) / 256, 256>>>(ei);

    static float *p_mean1 = nullptr, *p_mean2 = nullptr;
    static __half *p_xh = nullptr, *p_hh = nullptr;
    if (!p_mean1) {
        cudaGetSymbolAddress((void**)&p_mean1, g_mean1);
        cudaGetSymbolAddress((void**)&p_mean2, g_mean2);
        cudaGetSymbolAddress((void**)&p_xh, g_x_half);
        cudaGetSymbolAddress((void**)&p_hh, g_h_half);
    }

    // Layer 1
    agg1_kernel<<<888, 256>>>();
    mma_gemm_kernel<64, 1, 1><<<296, 256, SMEM1>>>(p_mean1, p_xh, Wl1, bl1, Wr1, p_hh);

    // Layer 2
    agg2_kernel<<<888, 256>>>();
    mma_gemm_kernel<128, 0, 0><<<148, 256, SMEM2>>>(p_mean2, p_hh, Wl2, bl2, Wr2, out);
}

// round 10
// speedup vs baseline: 2.5482x; 1.0025x over previous
#include <cuda_runtime.h>
#include <cuda_bf16.h>
#include <cuda_fp16.h>
#include <cstdint>

// Problem constants
#define N_NODES 100000
#define E_EDGES 1600000
#define F_IN 64
#define H_DIM 128

// ---------------- device scratch (no runtime allocation allowed) ----------------
__device__ int    g_cnt[N_NODES];
__device__ int    g_off[N_NODES];
__device__ int    g_cur[N_NODES];
__device__ int    g_srcs[E_EDGES];
__device__ int    g_blocksums[128];
__device__ __half g_x_half[(size_t)N_NODES * F_IN];
__device__ __half g_h_half[(size_t)N_NODES * H_DIM];
__device__ __half g_mean1h[(size_t)N_NODES * F_IN];   // layer-1 mean (fp16)
__device__ __half g_mean2h[(size_t)N_NODES * H_DIM];  // layer-2 mean (fp16)

// ---------------- prep: zero counters + convert x -> fp16 ----------------
__global__ void prep_kernel(const float* __restrict__ x) {
    int i = blockIdx.x * blockDim.x + threadIdx.x;
    if (i < N_NODES) g_cnt[i] = 0;
    if (i < N_NODES * (F_IN / 8)) {
        float4 f0 = ((const float4*)x)[i * 2 + 0];
        float4 f1 = ((const float4*)x)[i * 2 + 1];
        __half2 h0 = __floats2half2_rn(f0.x, f0.y);
        __half2 h1 = __floats2half2_rn(f0.z, f0.w);
        __half2 h2 = __floats2half2_rn(f1.x, f1.y);
        __half2 h3 = __floats2half2_rn(f1.z, f1.w);
        uint4 u;
        u.x = *(unsigned*)&h0; u.y = *(unsigned*)&h1;
        u.z = *(unsigned*)&h2; u.w = *(unsigned*)&h3;
        ((uint4*)g_x_half)[i] = u;
    }
}

// ---------------- CSR build ----------------
__global__ void count_kernel(const int* __restrict__ ei) {
    int e4 = blockIdx.x * blockDim.x + threadIdx.x;
    if (e4 < E_EDGES / 4) {
        int4 d = ((const int4*)(ei + E_EDGES))[e4];
        atomicAdd(&g_cnt[d.x], 1);
        atomicAdd(&g_cnt[d.y], 1);
        atomicAdd(&g_cnt[d.z], 1);
        atomicAdd(&g_cnt[d.w], 1);
    }
}

__global__ void scan_local_kernel() {
    __shared__ int s[1024];
    int i = blockIdx.x * 1024 + threadIdx.x;
    int v = (i < N_NODES) ? g_cnt[i] : 0;
    s[threadIdx.x] = v;
    __syncthreads();
    for (int d = 1; d < 1024; d <<= 1) {
        int t = (threadIdx.x >= d) ? s[threadIdx.x - d] : 0;
        __syncthreads();
        s[threadIdx.x] += t;
        __syncthreads();
    }
    if (i < N_NODES) g_off[i] = s[threadIdx.x] - v;
    if (threadIdx.x == 1023) g_blocksums[blockIdx.x] = s[1023];
}

// ALL threads hit EVERY barrier (no divergent barriers).
__global__ void scan_finish_kernel(int nblk) {
    __shared__ int bs[128];
    int tid = threadIdx.x;
    int v = 0;
    if (tid < 128) {
        v = (tid < nblk) ? g_blocksums[tid] : 0;
        bs[tid] = v;
    }
    __syncthreads();
    for (int d = 1; d < 128; d <<= 1) {
        int t = (tid < 128 && tid >= d) ? bs[tid - d] : 0;
        __syncthreads();
        if (tid < 128) bs[tid] += t;
        __syncthreads();
    }
    if (tid < 128) bs[tid] -= v;
    __syncthreads();
    int i = blockIdx.x * 1024 + tid;
    if (i < N_NODES) {
        int o = g_off[i] + bs[blockIdx.x];
        g_off[i] = o;
        g_cur[i] = o;
    }
}

__global__ void scatter_kernel(const int* __restrict__ ei) {
    int e4 = blockIdx.x * blockDim.x + threadIdx.x;
    if (e4 < E_EDGES / 4) {
        int4 s = ((const int4*)ei)[e4];
        int4 d = ((const int4*)(ei + E_EDGES))[e4];
        int p0 = atomicAdd(&g_cur[d.x], 1); g_srcs[p0] = s.x;
        int p1 = atomicAdd(&g_cur[d.y], 1); g_srcs[p1] = s.y;
        int p2 = atomicAdd(&g_cur[d.z], 1); g_srcs[p2] = s.z;
        int p3 = atomicAdd(&g_cur[d.w], 1); g_srcs[p3] = s.w;
    }
}

// ---------------- aggregation (mean of src fp16 features, fp32 acc, fp16 out)
__device__ __forceinline__ void acc_u4(float* a, uint4 u) {
    float2 f0 = __half22float2(*(__half2*)&u.x);
    float2 f1 = __half22float2(*(__half2*)&u.y);
    float2 f2 = __half22float2(*(__half2*)&u.z);
    float2 f3 = __half22float2(*(__half2*)&u.w);
    a[0] += f0.x; a[1] += f0.y; a[2] += f1.x; a[3] += f1.y;
    a[4] += f2.x; a[5] += f2.y; a[6] += f3.x; a[7] += f3.y;
}

// Grid-stride over nodes per lane-group. Scalar index loads (CSR offsets have
// arbitrary alignment — int4 loads there trap with misaligned address).
template <int LPN_LOG, int ROW_U4>
__device__ __forceinline__ void agg_body(const __half* __restrict__ feat,
                                         __half* __restrict__ mean) {
    int t = blockIdx.x * blockDim.x + threadIdx.x;
    int g0 = t >> LPN_LOG;
    int ngroups = (gridDim.x * blockDim.x) >> LPN_LOG;
    int c = t & ((1 << LPN_LOG) - 1);
    const uint4* f4 = (const uint4*)feat;
    for (int n = g0; n < N_NODES; n += ngroups) {
        int start = g_off[n];
        int deg = g_cnt[n];
        float a[8];
#pragma unroll
        for (int j = 0; j < 8; j++) a[j] = 0.f;
        int i = 0;
        for (; i + 8 <= deg; i += 8) {
            int s0 = g_srcs[start + i + 0];
            int s1 = g_srcs[start + i + 1];
            int s2 = g_srcs[start + i + 2];
            int s3 = g_srcs[start + i + 3];
            int s4 = g_srcs[start + i + 4];
            int s5 = g_srcs[start + i + 5];
            int s6 = g_srcs[start + i + 6];
            int s7 = g_srcs[start + i + 7];
            uint4 v0 = f4[(size_t)s0 * ROW_U4 + c];
            uint4 v1 = f4[(size_t)s1 * ROW_U4 + c];
            uint4 v2 = f4[(size_t)s2 * ROW_U4 + c];
            uint4 v3 = f4[(size_t)s3 * ROW_U4 + c];
            uint4 v4 = f4[(size_t)s4 * ROW_U4 + c];
            uint4 v5 = f4[(size_t)s5 * ROW_U4 + c];
            uint4 v6 = f4[(size_t)s6 * ROW_U4 + c];
            uint4 v7 = f4[(size_t)s7 * ROW_U4 + c];
            acc_u4(a, v0); acc_u4(a, v1); acc_u4(a, v2); acc_u4(a, v3);
            acc_u4(a, v4); acc_u4(a, v5); acc_u4(a, v6); acc_u4(a, v7);
        }
        for (; i < deg; i++) {
            int s0 = g_srcs[start + i];
            acc_u4(a, f4[(size_t)s0 * ROW_U4 + c]);
        }
        float inv = 1.0f / (float)(deg > 0 ? deg : 1);
        __half2 h0 = __floats2half2_rn(a[0] * inv, a[1] * inv);
        __half2 h1 = __floats2half2_rn(a[2] * inv, a[3] * inv);
        __half2 h2 = __floats2half2_rn(a[4] * inv, a[5] * inv);
        __half2 h3 = __floats2half2_rn(a[6] * inv, a[7] * inv);
        uint4 u;
        u.x = *(unsigned*)&h0; u.y = *(unsigned*)&h1;
        u.z = *(unsigned*)&h2; u.w = *(unsigned*)&h3;
        ((uint4*)mean)[(size_t)n * ROW_U4 + c] = u;
    }
}

__global__ void agg1_kernel() { agg_body<3, 8>(g_x_half, g_mean1h); }
__global__ void agg2_kernel() { agg_body<4, 16>(g_h_half, g_mean2h); }

// ---------------- fp16 tensor-core dual GEMM (m16n8k16) ----------------
// out[M,128] = [Amean | Aself] @ [Wl ; Wr]^T + bl  (optional relu)
// Both A operands fp16. Block: 256 thr = 8 warps as 2(row) x 4(col);
// warp tile 64x32. B in smem in k16-fragment order (half2 packed);
// A staged per-64-col chunk as fp16, row stride 36 u32 (conflict-free).

__device__ __forceinline__ void mma_f16(float* acc, unsigned a0, unsigned a1,
                                        unsigned a2, unsigned a3,
                                        unsigned b0, unsigned b1) {
    asm volatile(
        "mma.sync.aligned.m16n8k16.row.col.f32.f16.f16.f32 "
        "{%0,%1,%2,%3}, {%4,%5,%6,%7}, {%8,%9}, {%0,%1,%2,%3};"
        : "+f"(acc[0]), "+f"(acc[1]), "+f"(acc[2]), "+f"(acc[3])
        : "r"(a0), "r"(a1), "r"(a2), "r"(a3), "r"(b0), "r"(b1));
}

template <int K, int RELU, int OUT_HALF>
__global__ __launch_bounds__(256) void mma_gemm_kernel(
    const __half* __restrict__ Amean, const __half* __restrict__ Aself,
    const float* __restrict__ Wl, const float* __restrict__ bl,
    const float* __restrict__ Wr, void* __restrict__ out_v)
{
    constexpr int KK = 2 * K;
    constexpr int NCHUNK = KK / 64;
    constexpr int NKS = KK / 16;
    constexpr int NFRAG = NKS * 16;
    extern __shared__ unsigned smu[];
    unsigned* Bs = smu;                       // NFRAG * 64 u32 (half2 pairs)
    unsigned* As = smu + NFRAG * 64;          // 128 rows * 36 u32 (fp16)

    const int tid = threadIdx.x;
    const int lane = tid & 31;
    const int warp = tid >> 5;
    const int wr = warp & 1;
    const int wc = warp >> 1;
    const int gid = lane >> 2;
    const int tig = lane & 3;

    // Build B fragments (half2 packed):
    // Bs[frag*64 + l*2 + reg]: n = nt*8 + (l>>2), k = s*16 + (l&3)*2 + reg*8
    for (int idx = tid; idx < NFRAG * 64; idx += 256) {
        int frag = idx >> 6;
        int rem = idx & 63;
        int l = rem >> 1;
        int reg = rem & 1;
        int s = frag >> 4;
        int nt = frag & 15;
        int n = nt * 8 + (l >> 2);
        int k0 = s * 16 + (l & 3) * 2 + reg * 8;
        float v0, v1;
        if (k0 < K) { v0 = Wl[n * K + k0]; v1 = Wl[n * K + k0 + 1]; }
        else        { v0 = Wr[n * K + k0 - K]; v1 = Wr[n * K + k0 - K + 1]; }
        __half2 h = __floats2half2_rn(v0, v1);
        Bs[idx] = *(unsigned*)&h;
    }

    const int numTiles = (N_NODES + 127) / 128;   // 782
    for (int t = blockIdx.x; t < numTiles; t += gridDim.x) {
        int row0 = t * 128;
        float acc[4][4][4];
#pragma unroll
        for (int mt = 0; mt < 4; mt++)
#pragma unroll
            for (int nt = 0; nt < 4; nt++)
#pragma unroll
                for (int r = 0; r < 4; r++) acc[mt][nt][r] = 0.f;

        for (int c = 0; c < NCHUNK; c++) {
            bool isMean = (c * 64 < K);
            const __half* src = isMean ? Amean : Aself;
            int coff = isMean ? c * 64 : c * 64 - K;
            __syncthreads();
            // stage 128 rows x 64 cols of fp16; item = (row, 8-col group)
#pragma unroll
            for (int i = 0; i < 4; i++) {
                int item = tid + i * 256;
                int r = item >> 3;
                int j = item & 7;
                int grow = row0 + r;
                uint4 u = make_uint4(0, 0, 0, 0);
                if (grow < N_NODES)
                    u = *(const uint4*)(src + (size_t)grow * K + coff + j * 8);
                *(uint4*)(As + r * 36 + j * 4) = u;
            }
            __syncthreads();

#pragma unroll
            for (int s = 0; s < 4; s++) {
                unsigned af[4][4];
#pragma unroll
                for (int mt = 0; mt < 4; mt++) {
                    int r0 = wr * 64 + mt * 16 + gid;
                    af[mt][0] = As[(r0)     * 36 + s * 8 + tig];
                    af[mt][1] = As[(r0 + 8) * 36 + s * 8 + tig];
                    af[mt][2] = As[(r0)     * 36 + s * 8 + tig + 4];
                    af[mt][3] = As[(r0 + 8) * 36 + s * 8 + tig + 4];
                }
                int sg = c * 4 + s;
#pragma unroll
                for (int nt = 0; nt < 4; nt++) {
                    uint2 b = *(const uint2*)(Bs + (sg * 16 + wc * 4 + nt) * 64 + lane * 2);
#pragma unroll
                    for (int mt = 0; mt < 4; mt++)
                        mma_f16(acc[mt][nt], af[mt][0], af[mt][1], af[mt][2], af[mt][3],
                                b.x, b.y);
                }
            }
        }

        // epilogue: bias (+relu) + store
#pragma unroll
        for (int mt = 0; mt < 4; mt++) {
            int r0 = row0 + wr * 64 + mt * 16 + gid;
            int r1 = r0 + 8;
#pragma unroll
            for (int nt = 0; nt < 4; nt++) {
                int col = wc * 32 + nt * 8 + tig * 2;
                float2 bb = *(const float2*)(bl + col);
                float c0 = acc[mt][nt][0] + bb.x;
                float c1 = acc[mt][nt][1] + bb.y;
                float c2 = acc[mt][nt][2] + bb.x;
                float c3 = acc[mt][nt][3] + bb.y;
                if (RELU) {
                    c0 = fmaxf(c0, 0.f); c1 = fmaxf(c1, 0.f);
                    c2 = fmaxf(c2, 0.f); c3 = fmaxf(c3, 0.f);
                }
                if (OUT_HALF) {
                    __half* o = (__half*)out_v;
                    __half2 p0 = __floats2half2_rn(c0, c1);
                    __half2 p1 = __floats2half2_rn(c2, c3);
                    if (r0 < N_NODES) *(__half2*)(o + (size_t)r0 * 128 + col) = p0;
                    if (r1 < N_NODES) *(__half2*)(o + (size_t)r1 * 128 + col) = p1;
                } else {
                    float* o = (float*)out_v;
                    if (r0 < N_NODES)
                        *(float2*)(o + (size_t)r0 * 128 + col) = make_float2(c0, c1);
                    if (r1 < N_NODES)
                        *(float2*)(o + (size_t)r1 * 128 + col) = make_float2(c2, c3);
                }
            }
        }
    }
}

// ---------------- launch ----------------
extern "C" void kernel_launch(void* const* d_in, const int* in_sizes, int n_in,
                              void* d_out, int out_size)
{
    const float* x   = (const float*)d_in[0];
    const int*   ei  = (const int*)d_in[1];
    const float* Wl1 = (const float*)d_in[2];
    const float* bl1 = (const float*)d_in[3];
    const float* Wr1 = (const float*)d_in[4];
    const float* Wl2 = (const float*)d_in[5];
    const float* bl2 = (const float*)d_in[6];
    const float* Wr2 = (const float*)d_in[7];
    float* out = (float*)d_out;

    // smem: Bs = (2K/16)*16*64 u32, As = 128*36 u32
    const int SMEM1 = (8 * 16 * 64) * 4 + 128 * 36 * 4;    // 51200 B
    const int SMEM2 = (16 * 16 * 64) * 4 + 128 * 36 * 4;   // 83968 B

    static bool attr_done = false;
    if (!attr_done) {
        cudaFuncSetAttribute(mma_gemm_kernel<64, 1, 1>,
                             cudaFuncAttributeMaxDynamicSharedMemorySize, SMEM1);
        cudaFuncSetAttribute(mma_gemm_kernel<128, 0, 0>,
                             cudaFuncAttributeMaxDynamicSharedMemorySize, SMEM2);
        attr_done = true;
    }

    const int NBLK = (N_NODES + 1023) / 1024;   // 98

    // prep (zero counters + x->fp16), then CSR build
    prep_kernel<<<(N_NODES * (F_IN / 8) + 255) / 256, 256>>>(x);
    count_kernel<<<(E_EDGES / 4 + 255) / 256, 256>>>(ei);
    scan_local_kernel<<<NBLK, 1024>>>();
    scan_finish_kernel<<<NBLK, 1024>>>(NBLK);
    scatter_kernel<<<(E_EDGES / 4 + 255) / 256, 256>>>(ei);

    static __half *p_m1h = nullptr, *p_m2h = nullptr, *p_xh = nullptr, *p_hh = nullptr;
    if (!p_m1h) {
        cudaGetSymbolAddress((void**)&p_m1h, g_mean1h);
        cudaGetSymbolAddress((void**)&p_m2h, g_mean2h);
        cudaGetSymbolAddress((void**)&p_xh, g_x_half);
        cudaGetSymbolAddress((void**)&p_hh, g_h_half);
    }

    // Layer 1
    agg1_kernel<<<888, 256>>>();
    mma_gemm_kernel<64, 1, 1><<<296, 256, SMEM1>>>(p_m1h, p_xh, Wl1, bl1, Wr1, p_hh);

    // Layer 2
    agg2_kernel<<<888, 256>>>();
    mma_gemm_kernel<128, 0, 0><<<148, 256, SMEM2>>>(p_m2h, p_hh, Wl2, bl2, Wr2, out);
}